// round 4
// baseline (speedup 1.0000x reference)
#include <cuda_runtime.h>
#include <math.h>

#define SQ 512
#define HID 768
#define NHEAD 12
#define DHEAD 64
#define BATCH 8
#define NLAYER 12
#define FFDIM 3072
#define ROWS (BATCH*SQ)      /* 4096 */
#define BHT (BATCH*NHEAD)    /* 96   */

/* ---------------- scratch (device globals; no allocation allowed) -------- */
__device__ float g_x[ROWS*HID];
__device__ float g_h1[ROWS*HID];
__device__ float g_tmp[ROWS*HID];
__device__ float g_qb[ROWS*HID];
__device__ float g_kb[ROWS*HID];
__device__ float g_vb[ROWS*HID];
__device__ float g_ctx[ROWS*HID];
__device__ float g_ff[(size_t)ROWS*FFDIM];
__device__ float g_posk[SQ*HID];
__device__ float g_posq[SQ*HID];
__device__ float g_sc[(size_t)BHT*SQ*SQ];
__device__ float g_c2p[(size_t)BHT*SQ*SQ];
__device__ float g_p2c[(size_t)BHT*SQ*SQ];
__device__ int   g_cidx[1023];
__device__ int   g_pidx[1023];

/* ---------------- relative position bucket tables ------------------------ */
__device__ __forceinline__ int log_bucket(int rel) {
    const int mid = 128;
    float abs_pos;
    if (rel < mid && rel > -mid) abs_pos = (float)(mid - 1);
    else                         abs_pos = fabsf((float)rel);
    if (abs_pos <= (float)mid) return rel;
    float denom = (float)log(511.0 / 128.0);
    float log_pos = ceilf(logf(abs_pos / 128.0f) / denom * 127.0f) + 128.0f;
    float sgn = (rel > 0) ? 1.0f : ((rel < 0) ? -1.0f : 0.0f);
    return (int)(log_pos * sgn);
}

__global__ void build_tables_kernel() {
    int i = blockIdx.x * blockDim.x + threadIdx.x;
    if (i >= 1023) return;
    int d = i - 511;                       /* d = q - k */
    int c = log_bucket(d) + 256;           /* c2p index  */
    c = min(max(c, 0), 511);
    int p = 256 - log_bucket(-d);          /* p2c index  */
    p = min(max(p, 0), 511);
    g_cidx[i] = c;
    g_pidx[i] = p;
}

/* ---------------- embedding + masked layernorm --------------------------- */
__global__ void embed_kernel(const float* __restrict__ we, const float* __restrict__ pe,
                             const float* __restrict__ lg, const float* __restrict__ lb,
                             const int* __restrict__ ids, const int* __restrict__ am,
                             float* __restrict__ out) {
    __shared__ float red[256];
    int row = blockIdx.x, tid = threadIdx.x;
    int s = row & (SQ - 1);
    int id = ids[row];
    float v[3];
#pragma unroll
    for (int i = 0; i < 3; i++) {
        int c = tid + i * 256;
        v[i] = we[(size_t)id * HID + c] + pe[(size_t)s * HID + c];
    }
    float sum = v[0] + v[1] + v[2];
    red[tid] = sum; __syncthreads();
    for (int st = 128; st > 0; st >>= 1) { if (tid < st) red[tid] += red[tid + st]; __syncthreads(); }
    float mu = red[0] * (1.0f / HID);
    __syncthreads();
    float s2 = 0.f;
#pragma unroll
    for (int i = 0; i < 3; i++) { float d = v[i] - mu; s2 += d * d; }
    red[tid] = s2; __syncthreads();
    for (int st = 128; st > 0; st >>= 1) { if (tid < st) red[tid] += red[tid + st]; __syncthreads(); }
    float var = red[0] * (1.0f / HID);
    float r = rsqrtf(var + 1e-7f);
    float mf = (float)am[row];
    float* orow = out + (size_t)row * HID;
#pragma unroll
    for (int i = 0; i < 3; i++) {
        int c = tid + i * 256;
        orow[c] = ((v[i] - mu) * r * lg[c] + lb[c]) * mf;
    }
}

/* ---------------- layernorm ---------------------------------------------- */
__global__ void layernorm_kernel(const float* __restrict__ in, const float* __restrict__ lg,
                                 const float* __restrict__ lb, float* __restrict__ out) {
    __shared__ float red[256];
    int row = blockIdx.x, tid = threadIdx.x;
    const float* xr = in + (size_t)row * HID;
    float v[3];
#pragma unroll
    for (int i = 0; i < 3; i++) v[i] = xr[tid + i * 256];
    float sum = v[0] + v[1] + v[2];
    red[tid] = sum; __syncthreads();
    for (int st = 128; st > 0; st >>= 1) { if (tid < st) red[tid] += red[tid + st]; __syncthreads(); }
    float mu = red[0] * (1.0f / HID);
    __syncthreads();
    float s2 = 0.f;
#pragma unroll
    for (int i = 0; i < 3; i++) { float d = v[i] - mu; s2 += d * d; }
    red[tid] = s2; __syncthreads();
    for (int st = 128; st > 0; st >>= 1) { if (tid < st) red[tid] += red[tid + st]; __syncthreads(); }
    float var = red[0] * (1.0f / HID);
    float r = rsqrtf(var + 1e-7f);
    float* orow = out + (size_t)row * HID;
#pragma unroll
    for (int i = 0; i < 3; i++) {
        int c = tid + i * 256;
        orow[c] = (v[i] - mu) * r * lg[c] + lb[c];
    }
}

/* ---------------- batched tiled SGEMM ------------------------------------
   C[M,N] = A[M,K] @ B(,or B^T)[K,N] + bias + residual, optional exact GELU.
   batch z decomposed as (b = z/nh, h = z%nh); per-dim pointer offsets.      */
#define BM 128
#define BN 128
#define BKK 8
#define TM 8
#define TN 8

template<bool TRANSB>
__global__ __launch_bounds__(256, 2)
void gemm_kernel(const float* __restrict__ Abase, const float* __restrict__ Bbase,
                 const float* __restrict__ bias, const float* __restrict__ Rbase,
                 float* __restrict__ Cbase,
                 int M, int N, int K, int lda, int ldb, int ldc,
                 long long sAb, long long sAh, long long sBb, long long sBh,
                 long long sCb, long long sCh, int nh, int flags)
{
    __shared__ float As[BKK][BM];
    __shared__ float Bs[BKK][BN];
    int z = blockIdx.z;
    int bo = z / nh, ho = z - bo * nh;
    const float* A = Abase + (size_t)bo * sAb + (size_t)ho * sAh;
    const float* B = Bbase + (size_t)bo * sBb + (size_t)ho * sBh;
    float*       C = Cbase + (size_t)bo * sCb + (size_t)ho * sCh;

    int tid = threadIdx.x;
    int m0 = blockIdx.y * BM;
    int n0 = blockIdx.x * BN;

    int lRow = tid >> 1;            /* 0..127 */
    int lCol = (tid & 1) << 2;      /* 0 or 4 */
    int bRow = tid >> 5;            /* 0..7   */
    int bCol = (tid & 31) << 2;     /* 0..124 */

    int tx = tid & 15, ty = tid >> 4;
    int tm = ty * TM, tn = tx * TN;

    float acc[TM][TN];
#pragma unroll
    for (int i = 0; i < TM; i++)
#pragma unroll
        for (int j = 0; j < TN; j++) acc[i][j] = 0.f;

    for (int k0 = 0; k0 < K; k0 += BKK) {
        {
            float4 va = make_float4(0.f, 0.f, 0.f, 0.f);
            int gm = m0 + lRow;
            if (gm < M) va = *reinterpret_cast<const float4*>(A + (size_t)gm * lda + k0 + lCol);
            As[lCol + 0][lRow] = va.x; As[lCol + 1][lRow] = va.y;
            As[lCol + 2][lRow] = va.z; As[lCol + 3][lRow] = va.w;
        }
        if (TRANSB) {
            float4 vb = make_float4(0.f, 0.f, 0.f, 0.f);
            int gn = n0 + lRow;
            if (gn < N) vb = *reinterpret_cast<const float4*>(B + (size_t)gn * ldb + k0 + lCol);
            Bs[lCol + 0][lRow] = vb.x; Bs[lCol + 1][lRow] = vb.y;
            Bs[lCol + 2][lRow] = vb.z; Bs[lCol + 3][lRow] = vb.w;
        } else {
            float4 vb = make_float4(0.f, 0.f, 0.f, 0.f);
            int gn = n0 + bCol;
            if (gn < N) vb = *reinterpret_cast<const float4*>(B + (size_t)(k0 + bRow) * ldb + gn);
            *reinterpret_cast<float4*>(&Bs[bRow][bCol]) = vb;
        }
        __syncthreads();
#pragma unroll
        for (int kk = 0; kk < BKK; kk++) {
            float ra[TM], rb[TN];
#pragma unroll
            for (int i = 0; i < TM; i += 4)
                *reinterpret_cast<float4*>(ra + i) = *reinterpret_cast<const float4*>(&As[kk][tm + i]);
#pragma unroll
            for (int j = 0; j < TN; j += 4)
                *reinterpret_cast<float4*>(rb + j) = *reinterpret_cast<const float4*>(&Bs[kk][tn + j]);
#pragma unroll
            for (int i = 0; i < TM; i++)
#pragma unroll
                for (int j = 0; j < TN; j++) acc[i][j] += ra[i] * rb[j];
        }
        __syncthreads();
    }

    bool doGelu = (flags & 1) != 0;
    bool hasR   = (flags & 2) != 0;
#pragma unroll
    for (int i = 0; i < TM; i++) {
        int gm = m0 + tm + i;
        if (gm >= M) continue;
#pragma unroll
        for (int j = 0; j < TN; j++) {
            int gn = n0 + tn + j;
            if (gn >= N) continue;
            float c = acc[i][j];
            if (bias) c += bias[gn];
            if (hasR) c += Rbase[(size_t)gm * ldc + gn];
            if (doGelu) c = 0.5f * c * (1.0f + erff(c * 0.70710678118654752f));
            C[(size_t)gm * ldc + gn] = c;
        }
    }
}

/* ---------------- disentangled-bias gather + masked softmax -------------- */
__global__ void attn_softmax_kernel(float* __restrict__ sc, const float* __restrict__ c2p,
                                    const float* __restrict__ p2c, const int* __restrict__ am) {
    int q = blockIdx.x, bh = blockIdx.y;
    int b = bh / NHEAD;
    const float inv_scale = 0.07216878364870322f;  /* 1/sqrt(3*DH) */
    float* row = sc + ((size_t)bh * SQ + q) * SQ;
    const float* crow = c2p + ((size_t)bh * SQ + q) * SQ;
    const float* pbh  = p2c + (size_t)bh * SQ * SQ;
    int tid = threadIdx.x;
    bool mq = am[b * SQ + q] != 0;

    float v[2]; bool ok[2];
    float lmax = -3.402823466e38f;
#pragma unroll
    for (int i = 0; i < 2; i++) {
        int k = tid + i * 256;
        int di = q - k + 511;
        float s = (row[k] + crow[g_cidx[di]] + pbh[(size_t)k * SQ + g_pidx[di]]) * inv_scale;
        ok[i] = mq && (am[b * SQ + k] != 0);
        v[i] = ok[i] ? s : -3.402823466e38f;
        lmax = fmaxf(lmax, v[i]);
    }
    __shared__ float red[256];
    red[tid] = lmax; __syncthreads();
    for (int st = 128; st > 0; st >>= 1) { if (tid < st) red[tid] = fmaxf(red[tid], red[tid + st]); __syncthreads(); }
    float m = red[0]; __syncthreads();
    float ls = 0.f;
#pragma unroll
    for (int i = 0; i < 2; i++) { float e = expf(v[i] - m); v[i] = e; ls += e; }
    red[tid] = ls; __syncthreads();
    for (int st = 128; st > 0; st >>= 1) { if (tid < st) red[tid] += red[tid + st]; __syncthreads(); }
    float inv = 1.0f / red[0];
#pragma unroll
    for (int i = 0; i < 2; i++) {
        int k = tid + i * 256;
        row[k] = ok[i] ? v[i] * inv : 0.0f;
    }
}

/* ---------------- host orchestration ------------------------------------- */
extern "C" void kernel_launch(void* const* d_in, const int* in_sizes, int n_in,
                              void* d_out, int out_size) {
    const float* word_emb = (const float*)d_in[0];
    const float* pos_emb  = (const float*)d_in[1];
    const float* emb_ln_g = (const float*)d_in[2];
    const float* emb_ln_b = (const float*)d_in[3];
    const float* rel_emb  = (const float*)d_in[4];
    const float* Wq = (const float*)d_in[5];
    const float* bq = (const float*)d_in[6];
    const float* Wk = (const float*)d_in[7];
    const float* bk = (const float*)d_in[8];
    const float* Wv = (const float*)d_in[9];
    const float* bv = (const float*)d_in[10];
    const float* Wo = (const float*)d_in[11];
    const float* bo = (const float*)d_in[12];
    const float* ln1_g = (const float*)d_in[13];
    const float* ln1_b = (const float*)d_in[14];
    const float* Wi = (const float*)d_in[15];
    const float* bi = (const float*)d_in[16];
    const float* Wo2 = (const float*)d_in[17];
    const float* bo2 = (const float*)d_in[18];
    const float* ln2_g = (const float*)d_in[19];
    const float* ln2_b = (const float*)d_in[20];
    const int* input_ids = (const int*)d_in[21];
    const int* attn_mask = (const int*)d_in[22];
    float* out = (float*)d_out;

    float *x, *h1, *tmp, *qb, *kb, *vb, *ctx, *ff, *posk, *posq, *sc, *c2p, *p2c;
    cudaGetSymbolAddress((void**)&x,    g_x);
    cudaGetSymbolAddress((void**)&h1,   g_h1);
    cudaGetSymbolAddress((void**)&tmp,  g_tmp);
    cudaGetSymbolAddress((void**)&qb,   g_qb);
    cudaGetSymbolAddress((void**)&kb,   g_kb);
    cudaGetSymbolAddress((void**)&vb,   g_vb);
    cudaGetSymbolAddress((void**)&ctx,  g_ctx);
    cudaGetSymbolAddress((void**)&ff,   g_ff);
    cudaGetSymbolAddress((void**)&posk, g_posk);
    cudaGetSymbolAddress((void**)&posq, g_posq);
    cudaGetSymbolAddress((void**)&sc,   g_sc);
    cudaGetSymbolAddress((void**)&c2p,  g_c2p);
    cudaGetSymbolAddress((void**)&p2c,  g_p2c);

    dim3 blk(256);
    const long long SH = (long long)SQ * HID;       /* per-batch row stride */
    const long long SS = (long long)SQ * SQ;        /* per-head score tile  */
    const long long HSS = (long long)NHEAD * SS;    /* per-batch score blk  */

    build_tables_kernel<<<1, 1024>>>();
    embed_kernel<<<ROWS, 256>>>(word_emb, pos_emb, emb_ln_g, emb_ln_b, input_ids, attn_mask, x);

    for (int l = 0; l < NLAYER; l++) {
        const float* Wq_l = Wq + (size_t)l * HID * HID;
        const float* Wk_l = Wk + (size_t)l * HID * HID;
        const float* Wv_l = Wv + (size_t)l * HID * HID;
        const float* Wo_l = Wo + (size_t)l * HID * HID;
        const float* Wi_l = Wi + (size_t)l * HID * FFDIM;
        const float* Wo2_l = Wo2 + (size_t)l * FFDIM * HID;
        const float* bq_l = bq + (size_t)l * HID;
        const float* bk_l = bk + (size_t)l * HID;
        const float* bv_l = bv + (size_t)l * HID;
        const float* bo_l = bo + (size_t)l * HID;
        const float* bi_l = bi + (size_t)l * FFDIM;
        const float* bo2_l = bo2 + (size_t)l * HID;

        /* Q, K, V projections: [4096,768] = x @ W + b */
        gemm_kernel<false><<<dim3(6, 32, 1), blk>>>(x, Wq_l, bq_l, nullptr, qb,
            ROWS, HID, HID, HID, HID, HID, 0, 0, 0, 0, 0, 0, 1, 0);
        gemm_kernel<false><<<dim3(6, 32, 1), blk>>>(x, Wk_l, bk_l, nullptr, kb,
            ROWS, HID, HID, HID, HID, HID, 0, 0, 0, 0, 0, 0, 1, 0);
        gemm_kernel<false><<<dim3(6, 32, 1), blk>>>(x, Wv_l, bv_l, nullptr, vb,
            ROWS, HID, HID, HID, HID, HID, 0, 0, 0, 0, 0, 0, 1, 0);

        /* shared-key / shared-query position projections: [512,768] */
        gemm_kernel<false><<<dim3(6, 4, 1), blk>>>(rel_emb, Wk_l, bk_l, nullptr, posk,
            SQ, HID, HID, HID, HID, HID, 0, 0, 0, 0, 0, 0, 1, 0);
        gemm_kernel<false><<<dim3(6, 4, 1), blk>>>(rel_emb, Wq_l, bq_l, nullptr, posq,
            SQ, HID, HID, HID, HID, HID, 0, 0, 0, 0, 0, 0, 1, 0);

        /* raw scores QK^T per (b,h): [512,512,64] x 96 */
        gemm_kernel<true><<<dim3(4, 4, BHT), blk>>>(qb, kb, nullptr, nullptr, sc,
            SQ, SQ, DHEAD, HID, HID, SQ, SH, DHEAD, SH, DHEAD, HSS, SS, NHEAD, 0);
        /* c2p: Q @ pos_k^T */
        gemm_kernel<true><<<dim3(4, 4, BHT), blk>>>(qb, posk, nullptr, nullptr, c2p,
            SQ, SQ, DHEAD, HID, HID, SQ, SH, DHEAD, 0, DHEAD, HSS, SS, NHEAD, 0);
        /* p2c: K @ pos_q^T */
        gemm_kernel<true><<<dim3(4, 4, BHT), blk>>>(kb, posq, nullptr, nullptr, p2c,
            SQ, SQ, DHEAD, HID, HID, SQ, SH, DHEAD, 0, DHEAD, HSS, SS, NHEAD, 0);

        /* gather rel-pos terms + mask + softmax (in-place on sc) */
        attn_softmax_kernel<<<dim3(SQ, BHT), 256>>>(sc, c2p, p2c, attn_mask);

        /* ctx = probs @ V : [512,64,512] x 96, scattered into [B*S,H] layout */
        gemm_kernel<false><<<dim3(1, 4, BHT), blk>>>(sc, vb, nullptr, nullptr, ctx,
            SQ, DHEAD, SQ, SQ, HID, HID, HSS, SS, SH, DHEAD, SH, DHEAD, NHEAD, 0);

        /* output projection + residual, then LN -> h1 */
        gemm_kernel<false><<<dim3(6, 32, 1), blk>>>(ctx, Wo_l, bo_l, x, tmp,
            ROWS, HID, HID, HID, HID, HID, 0, 0, 0, 0, 0, 0, 1, 2);
        layernorm_kernel<<<ROWS, 256>>>(tmp, ln1_g + (size_t)l * HID, ln1_b + (size_t)l * HID, h1);

        /* FFN: gelu(h1 @ Wi + bi) @ Wo2 + bo2 + h1, then LN */
        gemm_kernel<false><<<dim3(24, 32, 1), blk>>>(h1, Wi_l, bi_l, nullptr, ff,
            ROWS, FFDIM, HID, HID, FFDIM, FFDIM, 0, 0, 0, 0, 0, 0, 1, 1);
        gemm_kernel<false><<<dim3(6, 32, 1), blk>>>(ff, Wo2_l, bo2_l, h1, tmp,
            ROWS, HID, FFDIM, FFDIM, HID, HID, 0, 0, 0, 0, 0, 0, 1, 2);
        layernorm_kernel<<<ROWS, 256>>>(tmp, ln2_g + (size_t)l * HID, ln2_b + (size_t)l * HID,
                                        (l == NLAYER - 1) ? out : x);
    }
}

// round 7
// speedup vs baseline: 2.2600x; 2.2600x over previous
#include <cuda_runtime.h>
#include <cuda_bf16.h>
#include <math.h>
#include <stdint.h>

#define SQ 512
#define HID 768
#define NHEAD 12
#define DHEAD 64
#define BATCH 8
#define NLAYER 12
#define FFDIM 3072
#define ROWS (BATCH*SQ)
#define BHT (BATCH*NHEAD)
#define HD (SQ*DHEAD)

#define WSZ (HID*HID)
#define WISZ (HID*FFDIM)
#define LOFF (4*WSZ + 2*WISZ)

/* ------------------------- scratch (device globals) ---------------------- */
__device__ float g_x[ROWS*HID];
__device__ float g_h1[ROWS*HID];
__device__ float g_tmp[ROWS*HID];
__device__ __nv_bfloat16 g_xh[ROWS*HID],  g_xl[ROWS*HID];
__device__ __nv_bfloat16 g_h1h[ROWS*HID], g_h1l[ROWS*HID];
__device__ __nv_bfloat16 g_qh[ROWS*HID],  g_ql[ROWS*HID];
__device__ __nv_bfloat16 g_kh[ROWS*HID],  g_kl[ROWS*HID];
__device__ __nv_bfloat16 g_vth[ROWS*HID], g_vtl[ROWS*HID];
__device__ __nv_bfloat16 g_ctxh[ROWS*HID],g_ctxl[ROWS*HID];
__device__ __nv_bfloat16 g_ffh[(size_t)ROWS*FFDIM], g_ffl[(size_t)ROWS*FFDIM];
__device__ __nv_bfloat16 g_pkh[NHEAD*HD], g_pkl[NHEAD*HD];
__device__ __nv_bfloat16 g_pqh[NHEAD*HD], g_pql[NHEAD*HD];
__device__ __nv_bfloat16 g_relh[SQ*HID],  g_rell[SQ*HID];
__device__ __nv_bfloat16 g_wth[(size_t)NLAYER*LOFF];
__device__ __nv_bfloat16 g_wtl[(size_t)NLAYER*LOFF];
__device__ float g_sc[(size_t)BHT*SQ*SQ];
__device__ float g_c2p[(size_t)BHT*SQ*SQ];
__device__ float g_p2c[(size_t)BHT*SQ*SQ];
__device__ __nv_bfloat16 g_ph[(size_t)BHT*SQ*SQ], g_pl[(size_t)BHT*SQ*SQ];
__device__ int g_cidx[1023], g_pidx[1023];

/* ------------------------- PTX helpers ----------------------------------- */
__device__ __forceinline__ uint32_t smem_u32(const void* p) {
    uint32_t a;
    asm("{ .reg .u64 t; cvta.to.shared.u64 t, %1; cvt.u32.u64 %0, t; }" : "=r"(a) : "l"(p));
    return a;
}
#define SWZ(x) ((x) ^ (((x) >> 3) & 0x70))

#define CPA16(dst, src) asm volatile("cp.async.cg.shared.global [%0], [%1], 16;" :: "r"(dst), "l"(src))
#define CPA_WAIT() asm volatile("cp.async.commit_group;\n\tcp.async.wait_group 0;" ::: "memory")

__device__ __forceinline__ void ldm4(uint32_t* r, uint32_t addr) {
    asm volatile("ldmatrix.sync.aligned.m8n8.x4.shared.b16 {%0,%1,%2,%3}, [%4];"
        : "=r"(r[0]), "=r"(r[1]), "=r"(r[2]), "=r"(r[3]) : "r"(addr));
}
__device__ __forceinline__ void mma16816(float* c, const uint32_t* a, uint32_t b0, uint32_t b1) {
    asm volatile("mma.sync.aligned.m16n8k16.row.col.f32.bf16.bf16.f32 "
        "{%0,%1,%2,%3}, {%4,%5,%6,%7}, {%8,%9}, {%0,%1,%2,%3};"
        : "+f"(c[0]), "+f"(c[1]), "+f"(c[2]), "+f"(c[3])
        : "r"(a[0]), "r"(a[1]), "r"(a[2]), "r"(a[3]), "r"(b0), "r"(b1));
}
/* A fragment addr: 16x16 tile at (mbase, k=16*ks) in row-major 128B-row swizzled smem */
__device__ __forceinline__ uint32_t amat_addr(uint32_t base, int mbase, int ks, int lane) {
    int mat = lane >> 3, rin = lane & 7;
    int m = mbase + rin + ((mat & 1) << 3);
    int quad = 2 * ks + (mat >> 1);
    return base + SWZ(m * 128 + quad * 16);
}
/* B fragment addr: n16 x k16 tile (B stored [n][k] K-major) */
__device__ __forceinline__ uint32_t bmat_addr(uint32_t base, int nbase, int ks, int lane) {
    int mat = lane >> 3, rin = lane & 7;
    int n = nbase + rin + ((mat >> 1) << 3);
    int quad = 2 * ks + (mat & 1);
    return base + SWZ(n * 128 + quad * 16);
}

/* ------------------------- rel-pos bucket tables -------------------------- */
__device__ __forceinline__ int log_bucket(int rel) {
    const int mid = 128;
    float abs_pos;
    if (rel < mid && rel > -mid) abs_pos = (float)(mid - 1);
    else                         abs_pos = fabsf((float)rel);
    if (abs_pos <= (float)mid) return rel;
    float denom = (float)log(511.0 / 128.0);
    float log_pos = ceilf(logf(abs_pos / 128.0f) / denom * 127.0f) + 128.0f;
    float sgn = (rel > 0) ? 1.0f : ((rel < 0) ? -1.0f : 0.0f);
    return (int)(log_pos * sgn);
}
__global__ void build_tables_kernel() {
    int i = blockIdx.x * blockDim.x + threadIdx.x;
    if (i >= 1023) return;
    int d = i - 511;
    int c = log_bucket(d) + 256;  c = min(max(c, 0), 511);
    int p = 256 - log_bucket(-d); p = min(max(p, 0), 511);
    g_cidx[i] = c; g_pidx[i] = p;
}

__device__ __forceinline__ void split1(float v, __nv_bfloat16& h, __nv_bfloat16& l) {
    h = __float2bfloat16(v);
    l = __float2bfloat16(v - __bfloat162float(h));
}

/* transpose + hi/lo split: dst[n*K+k] = split(src[k*N+n]) */
__global__ void wsplit_kernel(const float* __restrict__ src, __nv_bfloat16* __restrict__ dh,
                              __nv_bfloat16* __restrict__ dl, int K, int N,
                              long long sStride, long long dStride) {
    __shared__ float t[32][33];
    int l = blockIdx.z;
    const float* s = src + (size_t)l * sStride;
    __nv_bfloat16* oh = dh + (size_t)l * dStride;
    __nv_bfloat16* ol = dl + (size_t)l * dStride;
    int k0 = blockIdx.x * 32, n0 = blockIdx.y * 32;
    int tx = threadIdx.x, ty = threadIdx.y;
#pragma unroll
    for (int i = 0; i < 32; i += 8) t[ty + i][tx] = s[(size_t)(k0 + ty + i) * N + n0 + tx];
    __syncthreads();
#pragma unroll
    for (int i = 0; i < 32; i += 8) {
        float v = t[tx][ty + i];
        __nv_bfloat16 h, lo; split1(v, h, lo);
        size_t o = (size_t)(n0 + ty + i) * K + k0 + tx;
        oh[o] = h; ol[o] = lo;
    }
}

__global__ void split_kernel(const float* __restrict__ s, __nv_bfloat16* __restrict__ oh,
                             __nv_bfloat16* __restrict__ ol, int n) {
    int i = blockIdx.x * blockDim.x + threadIdx.x;
    if (i < n) { __nv_bfloat16 h, l; split1(s[i], h, l); oh[i] = h; ol[i] = l; }
}

/* ------------------------- embedding + masked LN -------------------------- */
__global__ void embed_kernel(const float* __restrict__ we, const float* __restrict__ pe,
                             const float* __restrict__ lg, const float* __restrict__ lb,
                             const int* __restrict__ ids, const int* __restrict__ am,
                             float* __restrict__ out, __nv_bfloat16* __restrict__ outh,
                             __nv_bfloat16* __restrict__ outl) {
    __shared__ float red[256];
    int row = blockIdx.x, tid = threadIdx.x;
    int s = row & (SQ - 1);
    int id = ids[row];
    float v[3];
#pragma unroll
    for (int i = 0; i < 3; i++) {
        int c = tid + i * 256;
        v[i] = we[(size_t)id * HID + c] + pe[(size_t)s * HID + c];
    }
    float sum = v[0] + v[1] + v[2];
    red[tid] = sum; __syncthreads();
    for (int st = 128; st > 0; st >>= 1) { if (tid < st) red[tid] += red[tid + st]; __syncthreads(); }
    float mu = red[0] * (1.0f / HID); __syncthreads();
    float s2 = 0.f;
#pragma unroll
    for (int i = 0; i < 3; i++) { float d = v[i] - mu; s2 += d * d; }
    red[tid] = s2; __syncthreads();
    for (int st = 128; st > 0; st >>= 1) { if (tid < st) red[tid] += red[tid + st]; __syncthreads(); }
    float r = rsqrtf(red[0] * (1.0f / HID) + 1e-7f);
    float mf = (float)am[row];
    size_t rb = (size_t)row * HID;
#pragma unroll
    for (int i = 0; i < 3; i++) {
        int c = tid + i * 256;
        float o = ((v[i] - mu) * r * lg[c] + lb[c]) * mf;
        out[rb + c] = o;
        __nv_bfloat16 h, l; split1(o, h, l);
        outh[rb + c] = h; outl[rb + c] = l;
    }
}

/* ------------------------- layernorm (+ optional hi/lo) ------------------- */
__global__ void ln_kernel(const float* __restrict__ in, const float* __restrict__ lg,
                          const float* __restrict__ lb, float* __restrict__ out,
                          __nv_bfloat16* __restrict__ outh, __nv_bfloat16* __restrict__ outl) {
    __shared__ float red[256];
    int row = blockIdx.x, tid = threadIdx.x;
    const float* xr = in + (size_t)row * HID;
    float v[3];
#pragma unroll
    for (int i = 0; i < 3; i++) v[i] = xr[tid + i * 256];
    float sum = v[0] + v[1] + v[2];
    red[tid] = sum; __syncthreads();
    for (int st = 128; st > 0; st >>= 1) { if (tid < st) red[tid] += red[tid + st]; __syncthreads(); }
    float mu = red[0] * (1.0f / HID); __syncthreads();
    float s2 = 0.f;
#pragma unroll
    for (int i = 0; i < 3; i++) { float d = v[i] - mu; s2 += d * d; }
    red[tid] = s2; __syncthreads();
    for (int st = 128; st > 0; st >>= 1) { if (tid < st) red[tid] += red[tid + st]; __syncthreads(); }
    float r = rsqrtf(red[0] * (1.0f / HID) + 1e-7f);
    size_t rb = (size_t)row * HID;
#pragma unroll
    for (int i = 0; i < 3; i++) {
        int c = tid + i * 256;
        float o = (v[i] - mu) * r * lg[c] + lb[c];
        out[rb + c] = o;
        if (outh) { __nv_bfloat16 h, l; split1(o, h, l); outh[rb + c] = h; outl[rb + c] = l; }
    }
}

/* ------------------------- softmax (gather + mask -> bf16 hi/lo) ---------- */
__global__ void attn_softmax_kernel(const float* __restrict__ sc, const float* __restrict__ c2p,
                                    const float* __restrict__ p2c, const int* __restrict__ am,
                                    __nv_bfloat16* __restrict__ ph, __nv_bfloat16* __restrict__ pl) {
    int q = blockIdx.x, bh = blockIdx.y;
    int b = bh / NHEAD;
    const float inv_scale = 0.07216878364870322f;
    const float* row  = sc  + ((size_t)bh * SQ + q) * SQ;
    const float* crow = c2p + ((size_t)bh * SQ + q) * SQ;
    const float* pbh  = p2c + (size_t)bh * SQ * SQ;
    int tid = threadIdx.x;
    bool mq = am[b * SQ + q] != 0;

    float v[2]; bool ok[2];
    float lmax = -3.402823466e38f;
#pragma unroll
    for (int i = 0; i < 2; i++) {
        int k = tid + i * 256;
        int di = q - k + 511;
        float s = (row[k] + crow[g_cidx[di]] + pbh[(size_t)k * SQ + g_pidx[di]]) * inv_scale;
        ok[i] = mq && (am[b * SQ + k] != 0);
        v[i] = ok[i] ? s : -3.402823466e38f;
        lmax = fmaxf(lmax, v[i]);
    }
    __shared__ float red[256];
    red[tid] = lmax; __syncthreads();
    for (int st = 128; st > 0; st >>= 1) { if (tid < st) red[tid] = fmaxf(red[tid], red[tid + st]); __syncthreads(); }
    float m = red[0]; __syncthreads();
    float ls = 0.f;
#pragma unroll
    for (int i = 0; i < 2; i++) { float e = expf(v[i] - m); v[i] = e; ls += e; }
    red[tid] = ls; __syncthreads();
    for (int st = 128; st > 0; st >>= 1) { if (tid < st) red[tid] += red[tid + st]; __syncthreads(); }
    float inv = 1.0f / red[0];
    size_t ob = ((size_t)bh * SQ + q) * SQ;
#pragma unroll
    for (int i = 0; i < 2; i++) {
        int k = tid + i * 256;
        float p = ok[i] ? v[i] * inv : 0.0f;
        __nv_bfloat16 h, l; split1(p, h, l);
        ph[ob + k] = h; pl[ob + k] = l;
    }
}

/* ------------------------- mma.sync split-bf16 GEMM ----------------------- */
#define KC 64
#define ABYTES 16384   /* 128 rows x 128B */

#define FL_GELU 1
#define FL_RES  2
#define FL_F32  4
#define FL_HILO 8
#define FL_HSC  16
#define FL_VT   32

__device__ __forceinline__ void epi_pair(
    float v0, float v1, int m, int n,
    const float* bias, const float* Rb, float* Cf,
    __nv_bfloat16* Chi, __nv_bfloat16* Clo,
    int ldc, int ldh, size_t cfoff, size_t hoff, int flags)
{
    if (bias) { v0 += __ldg(bias + n); v1 += __ldg(bias + n + 1); }
    if (flags & FL_RES) {
        float2 rv = *reinterpret_cast<const float2*>(Rb + (size_t)m * ldc + n);
        v0 += rv.x; v1 += rv.y;
    }
    if (flags & FL_GELU) {
        v0 = 0.5f * v0 * (1.0f + erff(v0 * 0.70710678118654752f));
        v1 = 0.5f * v1 * (1.0f + erff(v1 * 0.70710678118654752f));
    }
    if (flags & FL_F32) {
        float2* p = reinterpret_cast<float2*>(Cf + cfoff + (size_t)m * ldc + n);
        *p = make_float2(v0, v1);
    }
    if (flags & (FL_HILO | FL_HSC)) {
        size_t base;
        if (flags & FL_HSC)
            base = (size_t)(m >> 9) * ((size_t)NHEAD * HD) + (size_t)(n >> 6) * HD
                 + (size_t)(m & 511) * 64 + (n & 63);
        else
            base = hoff + (size_t)m * ldh + n;
        __nv_bfloat16 h0, l0, h1, l1;
        split1(v0, h0, l0); split1(v1, h1, l1);
        __nv_bfloat162 hh; hh.x = h0; hh.y = h1;
        __nv_bfloat162 ll; ll.x = l0; ll.y = l1;
        *reinterpret_cast<uint32_t*>(Chi + base) = *reinterpret_cast<uint32_t*>(&hh);
        *reinterpret_cast<uint32_t*>(Clo + base) = *reinterpret_cast<uint32_t*>(&ll);
    }
    if (flags & FL_VT) {
        size_t i0 = ((size_t)(m >> 9) * NHEAD + (n >> 6)) * ((size_t)64 * SQ)
                  + (size_t)(n & 63) * SQ + (m & 511);
        size_t i1 = ((size_t)(m >> 9) * NHEAD + ((n + 1) >> 6)) * ((size_t)64 * SQ)
                  + (size_t)((n + 1) & 63) * SQ + (m & 511);
        __nv_bfloat16 h, l;
        split1(v0, h, l); Chi[i0] = h; Clo[i0] = l;
        split1(v1, h, l); Chi[i1] = h; Clo[i1] = l;
    }
}

template<int TN>
__global__ __launch_bounds__(256)
void hmma_kernel(const __nv_bfloat16* __restrict__ Ah, const __nv_bfloat16* __restrict__ Al,
                 const __nv_bfloat16* __restrict__ Bh, const __nv_bfloat16* __restrict__ Bl,
                 const float* __restrict__ bias, const float* __restrict__ Rb,
                 float* __restrict__ Cf, __nv_bfloat16* __restrict__ Chi, __nv_bfloat16* __restrict__ Clo,
                 int K, int lda, int ldb, int ldc, int ldh,
                 long long sAb, long long sAh_, long long sBb, long long sBh_,
                 long long sCb, long long sCh_, long long sHb, long long sHh_,
                 int nh, int flags)
{
    extern __shared__ char smem[];
    const int BBYTES = TN * 128;
    uint32_t sb = smem_u32(smem);
    const uint32_t oAh = 0, oAl = ABYTES, oBh = 2 * ABYTES, oBl = 2 * ABYTES + BBYTES;

    int tid = threadIdx.x, wid = tid >> 5, lane = tid & 31;
    int z = blockIdx.z, bo = z / nh, ho = z - bo * nh;
    int m0 = blockIdx.y * 128, n0 = blockIdx.x * TN;

    const __nv_bfloat16* Azh = Ah + (size_t)bo * sAb + (size_t)ho * sAh_;
    const __nv_bfloat16* Azl = Al + (size_t)bo * sAb + (size_t)ho * sAh_;
    const __nv_bfloat16* Bzh = Bh + (size_t)bo * sBb + (size_t)ho * sBh_;
    const __nv_bfloat16* Bzl = Bl + (size_t)bo * sBb + (size_t)ho * sBh_;

    const int MI = (TN == 128) ? 2 : 1;
    int wm = (TN == 128) ? (wid & 3) * 32 : wid * 16;
    int wn = (TN == 128) ? (wid >> 2) * 64 : 0;

    float acc[(TN == 128) ? 2 : 1][8][4];
#pragma unroll
    for (int a = 0; a < MI; a++)
#pragma unroll
        for (int b = 0; b < 8; b++)
#pragma unroll
            for (int c = 0; c < 4; c++) acc[a][b][c] = 0.f;

    int nch = K / KC;
    for (int ch = 0; ch < nch; ch++) {
        int k0 = ch * KC;
        /* A tiles: 1024 16B quads each for hi and lo */
#pragma unroll
        for (int i = 0; i < 4; i++) {
            int q = tid + i * 256;
            int row = q >> 3, quad = q & 7;
            size_t goff = (size_t)(m0 + row) * lda + k0 + quad * 8;
            uint32_t so = SWZ(row * 128 + quad * 16);
            CPA16(sb + oAh + so, Azh + goff);
            CPA16(sb + oAl + so, Azl + goff);
        }
        /* B tiles: TN*8 quads each */
#pragma unroll
        for (int i = 0; i < TN / 32; i++) {
            int q = tid + i * 256;
            int row = q >> 3, quad = q & 7;
            size_t goff = (size_t)(n0 + row) * ldb + k0 + quad * 8;
            uint32_t so = SWZ(row * 128 + quad * 16);
            CPA16(sb + oBh + so, Bzh + goff);
            CPA16(sb + oBl + so, Bzl + goff);
        }
        CPA_WAIT();
        __syncthreads();

#pragma unroll
        for (int ks = 0; ks < 4; ks++) {
            uint32_t ah[(TN == 128) ? 2 : 1][4], al[(TN == 128) ? 2 : 1][4];
#pragma unroll
            for (int mi = 0; mi < MI; mi++) {
                ldm4(ah[mi], amat_addr(sb + oAh, wm + mi * 16, ks, lane));
                ldm4(al[mi], amat_addr(sb + oAl, wm + mi * 16, ks, lane));
            }
#pragma unroll
            for (int ng = 0; ng < 4; ng++) {
                uint32_t bh[4], bl[4];
                ldm4(bh, bmat_addr(sb + oBh, wn + ng * 16, ks, lane));
                ldm4(bl, bmat_addr(sb + oBl, wn + ng * 16, ks, lane));
#pragma unroll
                for (int mi = 0; mi < MI; mi++) {
                    mma16816(acc[mi][2 * ng],     ah[mi], bh[0], bh[1]);
                    mma16816(acc[mi][2 * ng],     ah[mi], bl[0], bl[1]);
                    mma16816(acc[mi][2 * ng],     al[mi], bh[0], bh[1]);
                    mma16816(acc[mi][2 * ng + 1], ah[mi], bh[2], bh[3]);
                    mma16816(acc[mi][2 * ng + 1], ah[mi], bl[2], bl[3]);
                    mma16816(acc[mi][2 * ng + 1], al[mi], bh[2], bh[3]);
                }
            }
        }
        __syncthreads();
    }

    size_t cfoff = (size_t)bo * sCb + (size_t)ho * sCh_;
    size_t hoff  = (size_t)bo * sHb + (size_t)ho * sHh_;
    int r0 = lane >> 2, cc = (lane & 3) * 2;
#pragma unroll
    for (int mi = 0; mi < MI; mi++) {
#pragma unroll
        for (int nf = 0; nf < 8; nf++) {
            int m_ = m0 + wm + mi * 16 + r0;
            int n_ = n0 + wn + nf * 8 + cc;
            epi_pair(acc[mi][nf][0], acc[mi][nf][1], m_,     n_, bias, Rb, Cf, Chi, Clo, ldc, ldh, cfoff, hoff, flags);
            epi_pair(acc[mi][nf][2], acc[mi][nf][3], m_ + 8, n_, bias, Rb, Cf, Chi, Clo, ldc, ldh, cfoff, hoff, flags);
        }
    }
}

/* ------------------------- host-side GEMM wrapper ------------------------- */
static void tmma(const __nv_bfloat16* Ah, const __nv_bfloat16* Al,
                 const __nv_bfloat16* Bh, const __nv_bfloat16* Bl,
                 const float* bias, const float* Rb,
                 float* Cf, __nv_bfloat16* Chi, __nv_bfloat16* Clo,
                 int M, int N, int K, int lda, int ldb, int ldc, int ldh,
                 long long sAb, long long sAh, long long sBb, long long sBh,
                 long long sCb, long long sCh, long long sHb, long long sHh,
                 int nh, int nz, int flags)
{
    if (N >= 128) {
        dim3 g(N / 128, M / 128, nz);
        hmma_kernel<128><<<g, 256, 2 * ABYTES + 2 * 128 * 128>>>(Ah, Al, Bh, Bl, bias, Rb, Cf, Chi, Clo,
            K, lda, ldb, ldc, ldh, sAb, sAh, sBb, sBh, sCb, sCh, sHb, sHh, nh, flags);
    } else {
        dim3 g(1, M / 128, nz);
        hmma_kernel<64><<<g, 256, 2 * ABYTES + 2 * 64 * 128>>>(Ah, Al, Bh, Bl, bias, Rb, Cf, Chi, Clo,
            K, lda, ldb, ldc, ldh, sAb, sAh, sBb, sBh, sCb, sCh, sHb, sHh, nh, flags);
    }
}

extern "C" void kernel_launch(void* const* d_in, const int* in_sizes, int n_in,
                              void* d_out, int out_size) {
    const float* word_emb = (const float*)d_in[0];
    const float* pos_emb  = (const float*)d_in[1];
    const float* emb_ln_g = (const float*)d_in[2];
    const float* emb_ln_b = (const float*)d_in[3];
    const float* rel_emb  = (const float*)d_in[4];
    const float* Wq = (const float*)d_in[5];
    const float* bq = (const float*)d_in[6];
    const float* Wk = (const float*)d_in[7];
    const float* bk = (const float*)d_in[8];
    const float* Wv = (const float*)d_in[9];
    const float* bv = (const float*)d_in[10];
    const float* Wo = (const float*)d_in[11];
    const float* bo = (const float*)d_in[12];
    const float* ln1_g = (const float*)d_in[13];
    const float* ln1_b = (const float*)d_in[14];
    const float* Wi = (const float*)d_in[15];
    const float* bi = (const float*)d_in[16];
    const float* Wo2 = (const float*)d_in[17];
    const float* bo2 = (const float*)d_in[18];
    const float* ln2_g = (const float*)d_in[19];
    const float* ln2_b = (const float*)d_in[20];
    const int* input_ids = (const int*)d_in[21];
    const int* attn_mask = (const int*)d_in[22];
    float* out = (float*)d_out;

    cudaFuncSetAttribute(hmma_kernel<128>, cudaFuncAttributeMaxDynamicSharedMemorySize, 2 * ABYTES + 2 * 128 * 128);
    cudaFuncSetAttribute(hmma_kernel<64>,  cudaFuncAttributeMaxDynamicSharedMemorySize, 2 * ABYTES + 2 * 64 * 128);

    float *x, *h1, *tmp, *sc, *c2p, *p2c;
    __nv_bfloat16 *xh, *xl, *h1h, *h1l, *qh, *ql, *kh, *kl, *vth, *vtl, *ctxh, *ctxl;
    __nv_bfloat16 *ffh, *ffl, *pkh, *pkl, *pqh, *pql, *relh, *rell, *wth, *wtl, *ph, *pl;
    cudaGetSymbolAddress((void**)&x, g_x);       cudaGetSymbolAddress((void**)&h1, g_h1);
    cudaGetSymbolAddress((void**)&tmp, g_tmp);
    cudaGetSymbolAddress((void**)&sc, g_sc);     cudaGetSymbolAddress((void**)&c2p, g_c2p);
    cudaGetSymbolAddress((void**)&p2c, g_p2c);
    cudaGetSymbolAddress((void**)&xh, g_xh);     cudaGetSymbolAddress((void**)&xl, g_xl);
    cudaGetSymbolAddress((void**)&h1h, g_h1h);   cudaGetSymbolAddress((void**)&h1l, g_h1l);
    cudaGetSymbolAddress((void**)&qh, g_qh);     cudaGetSymbolAddress((void**)&ql, g_ql);
    cudaGetSymbolAddress((void**)&kh, g_kh);     cudaGetSymbolAddress((void**)&kl, g_kl);
    cudaGetSymbolAddress((void**)&vth, g_vth);   cudaGetSymbolAddress((void**)&vtl, g_vtl);
    cudaGetSymbolAddress((void**)&ctxh, g_ctxh); cudaGetSymbolAddress((void**)&ctxl, g_ctxl);
    cudaGetSymbolAddress((void**)&ffh, g_ffh);   cudaGetSymbolAddress((void**)&ffl, g_ffl);
    cudaGetSymbolAddress((void**)&pkh, g_pkh);   cudaGetSymbolAddress((void**)&pkl, g_pkl);
    cudaGetSymbolAddress((void**)&pqh, g_pqh);   cudaGetSymbolAddress((void**)&pql, g_pql);
    cudaGetSymbolAddress((void**)&relh, g_relh); cudaGetSymbolAddress((void**)&rell, g_rell);
    cudaGetSymbolAddress((void**)&wth, g_wth);   cudaGetSymbolAddress((void**)&wtl, g_wtl);
    cudaGetSymbolAddress((void**)&ph, g_ph);     cudaGetSymbolAddress((void**)&pl, g_pl);

    build_tables_kernel<<<1, 1024>>>();

    dim3 tb(32, 8);
    wsplit_kernel<<<dim3(HID/32, HID/32, NLAYER), tb>>>(Wq,  wth + 0*WSZ,        wtl + 0*WSZ,        HID, HID,   (long long)WSZ,  (long long)LOFF);
    wsplit_kernel<<<dim3(HID/32, HID/32, NLAYER), tb>>>(Wk,  wth + 1*WSZ,        wtl + 1*WSZ,        HID, HID,   (long long)WSZ,  (long long)LOFF);
    wsplit_kernel<<<dim3(HID/32, HID/32, NLAYER), tb>>>(Wv,  wth + 2*WSZ,        wtl + 2*WSZ,        HID, HID,   (long long)WSZ,  (long long)LOFF);
    wsplit_kernel<<<dim3(HID/32, HID/32, NLAYER), tb>>>(Wo,  wth + 3*WSZ,        wtl + 3*WSZ,        HID, HID,   (long long)WSZ,  (long long)LOFF);
    wsplit_kernel<<<dim3(HID/32, FFDIM/32, NLAYER), tb>>>(Wi,  wth + 4*WSZ,      wtl + 4*WSZ,        HID, FFDIM, (long long)WISZ, (long long)LOFF);
    wsplit_kernel<<<dim3(FFDIM/32, HID/32, NLAYER), tb>>>(Wo2, wth + 4*WSZ+WISZ, wtl + 4*WSZ+WISZ,   FFDIM, HID, (long long)WISZ, (long long)LOFF);
    split_kernel<<<(SQ*HID + 255)/256, 256>>>(rel_emb, relh, rell, SQ*HID);

    embed_kernel<<<ROWS, 256>>>(word_emb, pos_emb, emb_ln_g, emb_ln_b, input_ids, attn_mask, x, xh, xl);

    const long long SS = (long long)SQ * SQ;
    const long long HSS = (long long)NHEAD * SS;
    const long long SHD = (long long)HD;
    const long long BHD = (long long)NHEAD * HD;

    for (int l = 0; l < NLAYER; l++) {
        const __nv_bfloat16 *WqTh = wth + (size_t)l*LOFF, *WqTl = wtl + (size_t)l*LOFF;
        const __nv_bfloat16 *WkTh = WqTh + WSZ,   *WkTl = WqTl + WSZ;
        const __nv_bfloat16 *WvTh = WqTh + 2*WSZ, *WvTl = WqTl + 2*WSZ;
        const __nv_bfloat16 *WoTh = WqTh + 3*WSZ, *WoTl = WqTl + 3*WSZ;
        const __nv_bfloat16 *WiTh = WqTh + 4*WSZ, *WiTl = WqTl + 4*WSZ;
        const __nv_bfloat16 *W2Th = WqTh + 4*WSZ + WISZ, *W2Tl = WqTl + 4*WSZ + WISZ;
        const float *bq_l = bq + (size_t)l*HID, *bk_l = bk + (size_t)l*HID, *bv_l = bv + (size_t)l*HID;
        const float *bo_l = bo + (size_t)l*HID, *bi_l = bi + (size_t)l*FFDIM, *bo2_l = bo2 + (size_t)l*HID;

        /* Q/K/V projections -> head-blocked hi/lo (V transposed for PV) */
        tmma(xh, xl, WqTh, WqTl, bq_l, nullptr, nullptr, qh, ql,
             ROWS, HID, HID, HID, HID, 0, 0, 0,0,0,0, 0,0,0,0, 1, 1, FL_HSC);
        tmma(xh, xl, WkTh, WkTl, bk_l, nullptr, nullptr, kh, kl,
             ROWS, HID, HID, HID, HID, 0, 0, 0,0,0,0, 0,0,0,0, 1, 1, FL_HSC);
        tmma(xh, xl, WvTh, WvTl, bv_l, nullptr, nullptr, vth, vtl,
             ROWS, HID, HID, HID, HID, 0, 0, 0,0,0,0, 0,0,0,0, 1, 1, FL_VT);
        /* shared-projection position keys/queries (head-blocked) */
        tmma(relh, rell, WkTh, WkTl, bk_l, nullptr, nullptr, pkh, pkl,
             SQ, HID, HID, HID, HID, 0, 0, 0,0,0,0, 0,0,0,0, 1, 1, FL_HSC);
        tmma(relh, rell, WqTh, WqTl, bq_l, nullptr, nullptr, pqh, pql,
             SQ, HID, HID, HID, HID, 0, 0, 0,0,0,0, 0,0,0,0, 1, 1, FL_HSC);

        /* QK^T, c2p, p2c (fp32 scores) */
        tmma(qh, ql, kh, kl, nullptr, nullptr, sc, nullptr, nullptr,
             SQ, SQ, DHEAD, DHEAD, DHEAD, SQ, 0,
             BHD, SHD, BHD, SHD, HSS, SS, 0, 0, NHEAD, BHT, FL_F32);
        tmma(qh, ql, pkh, pkl, nullptr, nullptr, c2p, nullptr, nullptr,
             SQ, SQ, DHEAD, DHEAD, DHEAD, SQ, 0,
             BHD, SHD, 0, SHD, HSS, SS, 0, 0, NHEAD, BHT, FL_F32);
        tmma(kh, kl, pqh, pql, nullptr, nullptr, p2c, nullptr, nullptr,
             SQ, SQ, DHEAD, DHEAD, DHEAD, SQ, 0,
             BHD, SHD, 0, SHD, HSS, SS, 0, 0, NHEAD, BHT, FL_F32);

        attn_softmax_kernel<<<dim3(SQ, BHT), 256>>>(sc, c2p, p2c, attn_mask, ph, pl);

        /* ctx = P @ V (N=64), scatter hi/lo into [B*S, H] */
        tmma(ph, pl, vth, vtl, nullptr, nullptr, nullptr, ctxh, ctxl,
             SQ, DHEAD, SQ, SQ, SQ, 0, HID,
             HSS, SS, BHD, SHD, 0, 0, (long long)SQ*HID, DHEAD, NHEAD, BHT, FL_HILO);

        /* output projection + residual -> LN1 */
        tmma(ctxh, ctxl, WoTh, WoTl, bo_l, x, tmp, nullptr, nullptr,
             ROWS, HID, HID, HID, HID, HID, 0, 0,0,0,0, 0,0,0,0, 1, 1, FL_F32 | FL_RES);
        ln_kernel<<<ROWS, 256>>>(tmp, ln1_g + (size_t)l*HID, ln1_b + (size_t)l*HID, h1, h1h, h1l);

        /* FFN */
        tmma(h1h, h1l, WiTh, WiTl, bi_l, nullptr, nullptr, ffh, ffl,
             ROWS, FFDIM, HID, HID, HID, 0, FFDIM, 0,0,0,0, 0,0,0,0, 1, 1, FL_GELU | FL_HILO);
        tmma(ffh, ffl, W2Th, W2Tl, bo2_l, h1, tmp, nullptr, nullptr,
             ROWS, HID, FFDIM, FFDIM, FFDIM, HID, 0, 0,0,0,0, 0,0,0,0, 1, 1, FL_F32 | FL_RES);
        ln_kernel<<<ROWS, 256>>>(tmp, ln2_g + (size_t)l*HID, ln2_b + (size_t)l*HID,
                                 (l == NLAYER - 1) ? out : x,
                                 (l == NLAYER - 1) ? nullptr : xh,
                                 (l == NLAYER - 1) ? nullptr : xl);
    }
}

// round 8
// speedup vs baseline: 2.4802x; 1.0974x over previous
#include <cuda_runtime.h>
#include <cuda_bf16.h>
#include <math.h>
#include <stdint.h>

#define SQ 512
#define HID 768
#define NHEAD 12
#define DHEAD 64
#define BATCH 8
#define NLAYER 12
#define FFDIM 3072
#define ROWS (BATCH*SQ)
#define BHT (BATCH*NHEAD)
#define HD (SQ*DHEAD)

#define WSZ (HID*HID)
#define WISZ (HID*FFDIM)
#define LOFF (4*WSZ + 2*WISZ)

/* ------------------------- scratch (device globals) ---------------------- */
__device__ float g_x[ROWS*HID];
__device__ float g_h1[ROWS*HID];
__device__ float g_tmp[ROWS*HID];
__device__ __nv_bfloat16 g_xh[ROWS*HID],  g_xl[ROWS*HID];
__device__ __nv_bfloat16 g_h1h[ROWS*HID], g_h1l[ROWS*HID];
__device__ __nv_bfloat16 g_qh[ROWS*HID],  g_ql[ROWS*HID];
__device__ __nv_bfloat16 g_kh[ROWS*HID],  g_kl[ROWS*HID];
__device__ __nv_bfloat16 g_vth[ROWS*HID], g_vtl[ROWS*HID];
__device__ __nv_bfloat16 g_ctxh[ROWS*HID],g_ctxl[ROWS*HID];
__device__ __nv_bfloat16 g_ffh[(size_t)ROWS*FFDIM], g_ffl[(size_t)ROWS*FFDIM];
__device__ __nv_bfloat16 g_pkh[NHEAD*HD], g_pkl[NHEAD*HD];
__device__ __nv_bfloat16 g_pqh[NHEAD*HD], g_pql[NHEAD*HD];
__device__ __nv_bfloat16 g_relh[SQ*HID],  g_rell[SQ*HID];
__device__ __nv_bfloat16 g_wth[(size_t)NLAYER*LOFF];
__device__ __nv_bfloat16 g_wtl[(size_t)NLAYER*LOFF];
__device__ float g_sc[(size_t)BHT*SQ*SQ];
__device__ float g_c2p[(size_t)BHT*SQ*SQ];
__device__ float g_p2c[(size_t)BHT*SQ*SQ];
__device__ __nv_bfloat16 g_ph[(size_t)BHT*SQ*SQ], g_pl[(size_t)BHT*SQ*SQ];
__device__ int g_cidx[1023], g_pidx[1023];

/* ------------------------- PTX helpers ----------------------------------- */
__device__ __forceinline__ uint32_t smem_u32(const void* p) {
    uint32_t a;
    asm("{ .reg .u64 t; cvta.to.shared.u64 t, %1; cvt.u32.u64 %0, t; }" : "=r"(a) : "l"(p));
    return a;
}
#define SWZ(x) ((x) ^ (((x) >> 3) & 0x70))

#define CPA16(dst, src) asm volatile("cp.async.cg.shared.global [%0], [%1], 16;" :: "r"(dst), "l"(src))
#define CPA_COMMIT() asm volatile("cp.async.commit_group;" ::: "memory")
#define CPA_WAIT1() asm volatile("cp.async.wait_group 1;" ::: "memory")
#define CPA_WAIT0() asm volatile("cp.async.wait_group 0;" ::: "memory")

__device__ __forceinline__ void ldm4(uint32_t* r, uint32_t addr) {
    asm volatile("ldmatrix.sync.aligned.m8n8.x4.shared.b16 {%0,%1,%2,%3}, [%4];"
        : "=r"(r[0]), "=r"(r[1]), "=r"(r[2]), "=r"(r[3]) : "r"(addr));
}
__device__ __forceinline__ void mma16816(float* c, const uint32_t* a, uint32_t b0, uint32_t b1) {
    asm volatile("mma.sync.aligned.m16n8k16.row.col.f32.bf16.bf16.f32 "
        "{%0,%1,%2,%3}, {%4,%5,%6,%7}, {%8,%9}, {%0,%1,%2,%3};"
        : "+f"(c[0]), "+f"(c[1]), "+f"(c[2]), "+f"(c[3])
        : "r"(a[0]), "r"(a[1]), "r"(a[2]), "r"(a[3]), "r"(b0), "r"(b1));
}
__device__ __forceinline__ uint32_t amat_addr(uint32_t base, int mbase, int ks, int lane) {
    int mat = lane >> 3, rin = lane & 7;
    int m = mbase + rin + ((mat & 1) << 3);
    int quad = 2 * ks + (mat >> 1);
    return base + SWZ(m * 128 + quad * 16);
}
__device__ __forceinline__ uint32_t bmat_addr(uint32_t base, int nbase, int ks, int lane) {
    int mat = lane >> 3, rin = lane & 7;
    int n = nbase + rin + ((mat >> 1) << 3);
    int quad = 2 * ks + (mat & 1);
    return base + SWZ(n * 128 + quad * 16);
}

/* ------------------------- rel-pos bucket tables -------------------------- */
__device__ __forceinline__ int log_bucket(int rel) {
    const int mid = 128;
    float abs_pos;
    if (rel < mid && rel > -mid) abs_pos = (float)(mid - 1);
    else                         abs_pos = fabsf((float)rel);
    if (abs_pos <= (float)mid) return rel;
    float denom = (float)log(511.0 / 128.0);
    float log_pos = ceilf(logf(abs_pos / 128.0f) / denom * 127.0f) + 128.0f;
    float sgn = (rel > 0) ? 1.0f : ((rel < 0) ? -1.0f : 0.0f);
    return (int)(log_pos * sgn);
}
__global__ void build_tables_kernel() {
    int i = blockIdx.x * blockDim.x + threadIdx.x;
    if (i >= 1023) return;
    int d = i - 511;
    int c = log_bucket(d) + 256;  c = min(max(c, 0), 511);
    int p = 256 - log_bucket(-d); p = min(max(p, 0), 511);
    g_cidx[i] = c; g_pidx[i] = p;
}

__device__ __forceinline__ void split1(float v, __nv_bfloat16& h, __nv_bfloat16& l) {
    h = __float2bfloat16(v);
    l = __float2bfloat16(v - __bfloat162float(h));
}

/* transpose + hi/lo split: dst[n*K+k] = split(src[k*N+n]) */
__global__ void wsplit_kernel(const float* __restrict__ src, __nv_bfloat16* __restrict__ dh,
                              __nv_bfloat16* __restrict__ dl, int K, int N,
                              long long sStride, long long dStride) {
    __shared__ float t[32][33];
    int l = blockIdx.z;
    const float* s = src + (size_t)l * sStride;
    __nv_bfloat16* oh = dh + (size_t)l * dStride;
    __nv_bfloat16* ol = dl + (size_t)l * dStride;
    int k0 = blockIdx.x * 32, n0 = blockIdx.y * 32;
    int tx = threadIdx.x, ty = threadIdx.y;
#pragma unroll
    for (int i = 0; i < 32; i += 8) t[ty + i][tx] = s[(size_t)(k0 + ty + i) * N + n0 + tx];
    __syncthreads();
#pragma unroll
    for (int i = 0; i < 32; i += 8) {
        float v = t[tx][ty + i];
        __nv_bfloat16 h, lo; split1(v, h, lo);
        size_t o = (size_t)(n0 + ty + i) * K + k0 + tx;
        oh[o] = h; ol[o] = lo;
    }
}

__global__ void split_kernel(const float* __restrict__ s, __nv_bfloat16* __restrict__ oh,
                             __nv_bfloat16* __restrict__ ol, int n) {
    int i = blockIdx.x * blockDim.x + threadIdx.x;
    if (i < n) { __nv_bfloat16 h, l; split1(s[i], h, l); oh[i] = h; ol[i] = l; }
}

/* ------------------------- embedding + masked LN -------------------------- */
__global__ void embed_kernel(const float* __restrict__ we, const float* __restrict__ pe,
                             const float* __restrict__ lg, const float* __restrict__ lb,
                             const int* __restrict__ ids, const int* __restrict__ am,
                             float* __restrict__ out, __nv_bfloat16* __restrict__ outh,
                             __nv_bfloat16* __restrict__ outl) {
    __shared__ float red[256];
    int row = blockIdx.x, tid = threadIdx.x;
    int s = row & (SQ - 1);
    int id = ids[row];
    float v[3];
#pragma unroll
    for (int i = 0; i < 3; i++) {
        int c = tid + i * 256;
        v[i] = we[(size_t)id * HID + c] + pe[(size_t)s * HID + c];
    }
    float sum = v[0] + v[1] + v[2];
    red[tid] = sum; __syncthreads();
    for (int st = 128; st > 0; st >>= 1) { if (tid < st) red[tid] += red[tid + st]; __syncthreads(); }
    float mu = red[0] * (1.0f / HID); __syncthreads();
    float s2 = 0.f;
#pragma unroll
    for (int i = 0; i < 3; i++) { float d = v[i] - mu; s2 += d * d; }
    red[tid] = s2; __syncthreads();
    for (int st = 128; st > 0; st >>= 1) { if (tid < st) red[tid] += red[tid + st]; __syncthreads(); }
    float r = rsqrtf(red[0] * (1.0f / HID) + 1e-7f);
    float mf = (float)am[row];
    size_t rb = (size_t)row * HID;
#pragma unroll
    for (int i = 0; i < 3; i++) {
        int c = tid + i * 256;
        float o = ((v[i] - mu) * r * lg[c] + lb[c]) * mf;
        out[rb + c] = o;
        __nv_bfloat16 h, l; split1(o, h, l);
        outh[rb + c] = h; outl[rb + c] = l;
    }
}

/* ------------------------- layernorm (+ optional hi/lo) ------------------- */
__global__ void ln_kernel(const float* __restrict__ in, const float* __restrict__ lg,
                          const float* __restrict__ lb, float* __restrict__ out,
                          __nv_bfloat16* __restrict__ outh, __nv_bfloat16* __restrict__ outl) {
    __shared__ float red[256];
    int row = blockIdx.x, tid = threadIdx.x;
    const float* xr = in + (size_t)row * HID;
    float v[3];
#pragma unroll
    for (int i = 0; i < 3; i++) v[i] = xr[tid + i * 256];
    float sum = v[0] + v[1] + v[2];
    red[tid] = sum; __syncthreads();
    for (int st = 128; st > 0; st >>= 1) { if (tid < st) red[tid] += red[tid + st]; __syncthreads(); }
    float mu = red[0] * (1.0f / HID); __syncthreads();
    float s2 = 0.f;
#pragma unroll
    for (int i = 0; i < 3; i++) { float d = v[i] - mu; s2 += d * d; }
    red[tid] = s2; __syncthreads();
    for (int st = 128; st > 0; st >>= 1) { if (tid < st) red[tid] += red[tid + st]; __syncthreads(); }
    float r = rsqrtf(red[0] * (1.0f / HID) + 1e-7f);
    size_t rb = (size_t)row * HID;
#pragma unroll
    for (int i = 0; i < 3; i++) {
        int c = tid + i * 256;
        float o = (v[i] - mu) * r * lg[c] + lb[c];
        out[rb + c] = o;
        if (outh) { __nv_bfloat16 h, l; split1(o, h, l); outh[rb + c] = h; outl[rb + c] = l; }
    }
}

/* ------------------------- softmax (gather + mask -> bf16 hi/lo) ---------- */
__global__ void attn_softmax_kernel(const float* __restrict__ sc, const float* __restrict__ c2p,
                                    const float* __restrict__ p2c, const int* __restrict__ am,
                                    __nv_bfloat16* __restrict__ ph, __nv_bfloat16* __restrict__ pl) {
    int q = blockIdx.x, bh = blockIdx.y;
    int b = bh / NHEAD;
    const float inv_scale = 0.07216878364870322f;
    const float* row  = sc  + ((size_t)bh * SQ + q) * SQ;
    const float* crow = c2p + ((size_t)bh * SQ + q) * SQ;
    const float* pbh  = p2c + (size_t)bh * SQ * SQ;
    int tid = threadIdx.x;
    bool mq = am[b * SQ + q] != 0;

    float v[2]; bool ok[2];
    float lmax = -3.402823466e38f;
#pragma unroll
    for (int i = 0; i < 2; i++) {
        int k = tid + i * 256;
        int di = q - k + 511;
        float s = (row[k] + crow[g_cidx[di]] + pbh[(size_t)k * SQ + g_pidx[di]]) * inv_scale;
        ok[i] = mq && (am[b * SQ + k] != 0);
        v[i] = ok[i] ? s : -3.402823466e38f;
        lmax = fmaxf(lmax, v[i]);
    }
    __shared__ float red[256];
    red[tid] = lmax; __syncthreads();
    for (int st = 128; st > 0; st >>= 1) { if (tid < st) red[tid] = fmaxf(red[tid], red[tid + st]); __syncthreads(); }
    float m = red[0]; __syncthreads();
    float ls = 0.f;
#pragma unroll
    for (int i = 0; i < 2; i++) { float e = expf(v[i] - m); v[i] = e; ls += e; }
    red[tid] = ls; __syncthreads();
    for (int st = 128; st > 0; st >>= 1) { if (tid < st) red[tid] += red[tid + st]; __syncthreads(); }
    float inv = 1.0f / red[0];
    size_t ob = ((size_t)bh * SQ + q) * SQ;
#pragma unroll
    for (int i = 0; i < 2; i++) {
        int k = tid + i * 256;
        float p = ok[i] ? v[i] * inv : 0.0f;
        __nv_bfloat16 h, l; split1(p, h, l);
        ph[ob + k] = h; pl[ob + k] = l;
    }
}

/* ------------------------- mma.sync split-bf16 GEMM (2-stage pipe) -------- */
#define KC 64
#define ABYTES 16384   /* 128 rows x 128B */

#define FL_GELU 1
#define FL_RES  2
#define FL_F32  4
#define FL_HILO 8
#define FL_HSC  16
#define FL_VT   32

__device__ __forceinline__ void epi_pair(
    float v0, float v1, int m, int n,
    const float* bias, const float* Rb, float* Cf,
    __nv_bfloat16* Chi, __nv_bfloat16* Clo,
    int ldc, int ldh, size_t cfoff, size_t hoff, int flags)
{
    if (bias) { v0 += __ldg(bias + n); v1 += __ldg(bias + n + 1); }
    if (flags & FL_RES) {
        float2 rv = *reinterpret_cast<const float2*>(Rb + (size_t)m * ldc + n);
        v0 += rv.x; v1 += rv.y;
    }
    if (flags & FL_GELU) {
        v0 = 0.5f * v0 * (1.0f + erff(v0 * 0.70710678118654752f));
        v1 = 0.5f * v1 * (1.0f + erff(v1 * 0.70710678118654752f));
    }
    if (flags & FL_F32) {
        float2* p = reinterpret_cast<float2*>(Cf + cfoff + (size_t)m * ldc + n);
        *p = make_float2(v0, v1);
    }
    if (flags & (FL_HILO | FL_HSC)) {
        size_t base;
        if (flags & FL_HSC)
            base = (size_t)(m >> 9) * ((size_t)NHEAD * HD) + (size_t)(n >> 6) * HD
                 + (size_t)(m & 511) * 64 + (n & 63);
        else
            base = hoff + (size_t)m * ldh + n;
        __nv_bfloat16 h0, l0, h1, l1;
        split1(v0, h0, l0); split1(v1, h1, l1);
        __nv_bfloat162 hh; hh.x = h0; hh.y = h1;
        __nv_bfloat162 ll; ll.x = l0; ll.y = l1;
        *reinterpret_cast<uint32_t*>(Chi + base) = *reinterpret_cast<uint32_t*>(&hh);
        *reinterpret_cast<uint32_t*>(Clo + base) = *reinterpret_cast<uint32_t*>(&ll);
    }
    if (flags & FL_VT) {
        size_t i0 = ((size_t)(m >> 9) * NHEAD + (n >> 6)) * ((size_t)64 * SQ)
                  + (size_t)(n & 63) * SQ + (m & 511);
        size_t i1 = ((size_t)(m >> 9) * NHEAD + ((n + 1) >> 6)) * ((size_t)64 * SQ)
                  + (size_t)((n + 1) & 63) * SQ + (m & 511);
        __nv_bfloat16 h, l;
        split1(v0, h, l); Chi[i0] = h; Clo[i0] = l;
        split1(v1, h, l); Chi[i1] = h; Clo[i1] = l;
    }
}

template<int TN>
__device__ __forceinline__ void load_chunk(
    uint32_t sst, const __nv_bfloat16* Azh, const __nv_bfloat16* Azl,
    const __nv_bfloat16* Bzh, const __nv_bfloat16* Bzl,
    int m0, int n0, int k0, int lda, int ldb, int tid)
{
    const uint32_t oAl = ABYTES, oBh = 2 * ABYTES, oBl = 2 * ABYTES + TN * 128;
#pragma unroll
    for (int i = 0; i < 4; i++) {
        int q = tid + i * 256;
        int row = q >> 3, quad = q & 7;
        size_t goff = (size_t)(m0 + row) * lda + k0 + quad * 8;
        uint32_t so = SWZ(row * 128 + quad * 16);
        CPA16(sst + so, Azh + goff);
        CPA16(sst + oAl + so, Azl + goff);
    }
#pragma unroll
    for (int i = 0; i < TN / 32; i++) {
        int q = tid + i * 256;
        int row = q >> 3, quad = q & 7;
        size_t goff = (size_t)(n0 + row) * ldb + k0 + quad * 8;
        uint32_t so = SWZ(row * 128 + quad * 16);
        CPA16(sst + oBh + so, Bzh + goff);
        CPA16(sst + oBl + so, Bzl + goff);
    }
    CPA_COMMIT();
}

template<int TN>
__global__ __launch_bounds__(256)
void hmma_kernel(const __nv_bfloat16* __restrict__ Ah, const __nv_bfloat16* __restrict__ Al,
                 const __nv_bfloat16* __restrict__ Bh, const __nv_bfloat16* __restrict__ Bl,
                 const float* __restrict__ bias, const float* __restrict__ Rb,
                 float* __restrict__ Cf, __nv_bfloat16* __restrict__ Chi, __nv_bfloat16* __restrict__ Clo,
                 int K, int lda, int ldb, int ldc, int ldh,
                 long long sAb, long long sAh_, long long sBb, long long sBh_,
                 long long sCb, long long sCh_, long long sHb, long long sHh_,
                 int nh, int flags)
{
    extern __shared__ char smem[];
    const int STAGE = 2 * ABYTES + 2 * TN * 128;
    uint32_t sb = smem_u32(smem);

    int tid = threadIdx.x, wid = tid >> 5, lane = tid & 31;
    int z = blockIdx.z, bo = z / nh, ho = z - bo * nh;
    int m0 = blockIdx.y * 128, n0 = blockIdx.x * TN;

    const __nv_bfloat16* Azh = Ah + (size_t)bo * sAb + (size_t)ho * sAh_;
    const __nv_bfloat16* Azl = Al + (size_t)bo * sAb + (size_t)ho * sAh_;
    const __nv_bfloat16* Bzh = Bh + (size_t)bo * sBb + (size_t)ho * sBh_;
    const __nv_bfloat16* Bzl = Bl + (size_t)bo * sBb + (size_t)ho * sBh_;

    const int MI = (TN == 128) ? 2 : 1;
    int wm = (TN == 128) ? (wid & 3) * 32 : wid * 16;
    int wn = (TN == 128) ? (wid >> 2) * 64 : 0;

    float acc[(TN == 128) ? 2 : 1][8][4];
#pragma unroll
    for (int a = 0; a < MI; a++)
#pragma unroll
        for (int b = 0; b < 8; b++)
#pragma unroll
            for (int c = 0; c < 4; c++) acc[a][b][c] = 0.f;

    int nch = K / KC;
    load_chunk<TN>(sb, Azh, Azl, Bzh, Bzl, m0, n0, 0, lda, ldb, tid);

    for (int ch = 0; ch < nch; ch++) {
        if (ch + 1 < nch) {
            load_chunk<TN>(sb + ((ch + 1) & 1) * STAGE, Azh, Azl, Bzh, Bzl,
                           m0, n0, (ch + 1) * KC, lda, ldb, tid);
            CPA_WAIT1();
        } else {
            CPA_WAIT0();
        }
        __syncthreads();

        uint32_t st = sb + (ch & 1) * STAGE;
        const uint32_t oAl = ABYTES, oBh = 2 * ABYTES, oBl = 2 * ABYTES + TN * 128;
#pragma unroll
        for (int ks = 0; ks < 4; ks++) {
            uint32_t ah[(TN == 128) ? 2 : 1][4], al[(TN == 128) ? 2 : 1][4];
#pragma unroll
            for (int mi = 0; mi < MI; mi++) {
                ldm4(ah[mi], amat_addr(st, wm + mi * 16, ks, lane));
                ldm4(al[mi], amat_addr(st + oAl, wm + mi * 16, ks, lane));
            }
#pragma unroll
            for (int ng = 0; ng < 4; ng++) {
                uint32_t bh[4], bl[4];
                ldm4(bh, bmat_addr(st + oBh, wn + ng * 16, ks, lane));
                ldm4(bl, bmat_addr(st + oBl, wn + ng * 16, ks, lane));
#pragma unroll
                for (int mi = 0; mi < MI; mi++) {
                    mma16816(acc[mi][2 * ng],     ah[mi], bh[0], bh[1]);
                    mma16816(acc[mi][2 * ng],     ah[mi], bl[0], bl[1]);
                    mma16816(acc[mi][2 * ng],     al[mi], bh[0], bh[1]);
                    mma16816(acc[mi][2 * ng + 1], ah[mi], bh[2], bh[3]);
                    mma16816(acc[mi][2 * ng + 1], ah[mi], bl[2], bl[3]);
                    mma16816(acc[mi][2 * ng + 1], al[mi], bh[2], bh[3]);
                }
            }
        }
        __syncthreads();
    }

    size_t cfoff = (size_t)bo * sCb + (size_t)ho * sCh_;
    size_t hoff  = (size_t)bo * sHb + (size_t)ho * sHh_;
    int r0 = lane >> 2, cc = (lane & 3) * 2;
#pragma unroll
    for (int mi = 0; mi < MI; mi++) {
#pragma unroll
        for (int nf = 0; nf < 8; nf++) {
            int m_ = m0 + wm + mi * 16 + r0;
            int n_ = n0 + wn + nf * 8 + cc;
            epi_pair(acc[mi][nf][0], acc[mi][nf][1], m_,     n_, bias, Rb, Cf, Chi, Clo, ldc, ldh, cfoff, hoff, flags);
            epi_pair(acc[mi][nf][2], acc[mi][nf][3], m_ + 8, n_, bias, Rb, Cf, Chi, Clo, ldc, ldh, cfoff, hoff, flags);
        }
    }
}

/* ------------------------- host-side GEMM wrapper ------------------------- */
#define SMEM128 (2 * (2 * ABYTES + 2 * 128 * 128))
#define SMEM64  (2 * (2 * ABYTES + 2 * 64 * 128))

static void tmma(const __nv_bfloat16* Ah, const __nv_bfloat16* Al,
                 const __nv_bfloat16* Bh, const __nv_bfloat16* Bl,
                 const float* bias, const float* Rb,
                 float* Cf, __nv_bfloat16* Chi, __nv_bfloat16* Clo,
                 int M, int N, int K, int lda, int ldb, int ldc, int ldh,
                 long long sAb, long long sAh, long long sBb, long long sBh,
                 long long sCb, long long sCh, long long sHb, long long sHh,
                 int nh, int nz, int flags)
{
    if (N >= 128) {
        dim3 g(N / 128, M / 128, nz);
        hmma_kernel<128><<<g, 256, SMEM128>>>(Ah, Al, Bh, Bl, bias, Rb, Cf, Chi, Clo,
            K, lda, ldb, ldc, ldh, sAb, sAh, sBb, sBh, sCb, sCh, sHb, sHh, nh, flags);
    } else {
        dim3 g(1, M / 128, nz);
        hmma_kernel<64><<<g, 256, SMEM64>>>(Ah, Al, Bh, Bl, bias, Rb, Cf, Chi, Clo,
            K, lda, ldb, ldc, ldh, sAb, sAh, sBb, sBh, sCb, sCh, sHb, sHh, nh, flags);
    }
}

extern "C" void kernel_launch(void* const* d_in, const int* in_sizes, int n_in,
                              void* d_out, int out_size) {
    const float* word_emb = (const float*)d_in[0];
    const float* pos_emb  = (const float*)d_in[1];
    const float* emb_ln_g = (const float*)d_in[2];
    const float* emb_ln_b = (const float*)d_in[3];
    const float* rel_emb  = (const float*)d_in[4];
    const float* Wq = (const float*)d_in[5];
    const float* bq = (const float*)d_in[6];
    const float* Wk = (const float*)d_in[7];
    const float* bk = (const float*)d_in[8];
    const float* Wv = (const float*)d_in[9];
    const float* bv = (const float*)d_in[10];
    const float* Wo = (const float*)d_in[11];
    const float* bo = (const float*)d_in[12];
    const float* ln1_g = (const float*)d_in[13];
    const float* ln1_b = (const float*)d_in[14];
    const float* Wi = (const float*)d_in[15];
    const float* bi = (const float*)d_in[16];
    const float* Wo2 = (const float*)d_in[17];
    const float* bo2 = (const float*)d_in[18];
    const float* ln2_g = (const float*)d_in[19];
    const float* ln2_b = (const float*)d_in[20];
    const int* input_ids = (const int*)d_in[21];
    const int* attn_mask = (const int*)d_in[22];
    float* out = (float*)d_out;

    cudaFuncSetAttribute(hmma_kernel<128>, cudaFuncAttributeMaxDynamicSharedMemorySize, SMEM128);
    cudaFuncSetAttribute(hmma_kernel<64>,  cudaFuncAttributeMaxDynamicSharedMemorySize, SMEM64);

    float *x, *h1, *tmp, *sc, *c2p, *p2c;
    __nv_bfloat16 *xh, *xl, *h1h, *h1l, *qh, *ql, *kh, *kl, *vth, *vtl, *ctxh, *ctxl;
    __nv_bfloat16 *ffh, *ffl, *pkh, *pkl, *pqh, *pql, *relh, *rell, *wth, *wtl, *ph, *pl;
    cudaGetSymbolAddress((void**)&x, g_x);       cudaGetSymbolAddress((void**)&h1, g_h1);
    cudaGetSymbolAddress((void**)&tmp, g_tmp);
    cudaGetSymbolAddress((void**)&sc, g_sc);     cudaGetSymbolAddress((void**)&c2p, g_c2p);
    cudaGetSymbolAddress((void**)&p2c, g_p2c);
    cudaGetSymbolAddress((void**)&xh, g_xh);     cudaGetSymbolAddress((void**)&xl, g_xl);
    cudaGetSymbolAddress((void**)&h1h, g_h1h);   cudaGetSymbolAddress((void**)&h1l, g_h1l);
    cudaGetSymbolAddress((void**)&qh, g_qh);     cudaGetSymbolAddress((void**)&ql, g_ql);
    cudaGetSymbolAddress((void**)&kh, g_kh);     cudaGetSymbolAddress((void**)&kl, g_kl);
    cudaGetSymbolAddress((void**)&vth, g_vth);   cudaGetSymbolAddress((void**)&vtl, g_vtl);
    cudaGetSymbolAddress((void**)&ctxh, g_ctxh); cudaGetSymbolAddress((void**)&ctxl, g_ctxl);
    cudaGetSymbolAddress((void**)&ffh, g_ffh);   cudaGetSymbolAddress((void**)&ffl, g_ffl);
    cudaGetSymbolAddress((void**)&pkh, g_pkh);   cudaGetSymbolAddress((void**)&pkl, g_pkl);
    cudaGetSymbolAddress((void**)&pqh, g_pqh);   cudaGetSymbolAddress((void**)&pql, g_pql);
    cudaGetSymbolAddress((void**)&relh, g_relh); cudaGetSymbolAddress((void**)&rell, g_rell);
    cudaGetSymbolAddress((void**)&wth, g_wth);   cudaGetSymbolAddress((void**)&wtl, g_wtl);
    cudaGetSymbolAddress((void**)&ph, g_ph);     cudaGetSymbolAddress((void**)&pl, g_pl);

    build_tables_kernel<<<1, 1024>>>();

    dim3 tb(32, 8);
    wsplit_kernel<<<dim3(HID/32, HID/32, NLAYER), tb>>>(Wq,  wth + 0*WSZ,        wtl + 0*WSZ,        HID, HID,   (long long)WSZ,  (long long)LOFF);
    wsplit_kernel<<<dim3(HID/32, HID/32, NLAYER), tb>>>(Wk,  wth + 1*WSZ,        wtl + 1*WSZ,        HID, HID,   (long long)WSZ,  (long long)LOFF);
    wsplit_kernel<<<dim3(HID/32, HID/32, NLAYER), tb>>>(Wv,  wth + 2*WSZ,        wtl + 2*WSZ,        HID, HID,   (long long)WSZ,  (long long)LOFF);
    wsplit_kernel<<<dim3(HID/32, HID/32, NLAYER), tb>>>(Wo,  wth + 3*WSZ,        wtl + 3*WSZ,        HID, HID,   (long long)WSZ,  (long long)LOFF);
    wsplit_kernel<<<dim3(HID/32, FFDIM/32, NLAYER), tb>>>(Wi,  wth + 4*WSZ,      wtl + 4*WSZ,        HID, FFDIM, (long long)WISZ, (long long)LOFF);
    wsplit_kernel<<<dim3(FFDIM/32, HID/32, NLAYER), tb>>>(Wo2, wth + 4*WSZ+WISZ, wtl + 4*WSZ+WISZ,   FFDIM, HID, (long long)WISZ, (long long)LOFF);
    split_kernel<<<(SQ*HID + 255)/256, 256>>>(rel_emb, relh, rell, SQ*HID);

    embed_kernel<<<ROWS, 256>>>(word_emb, pos_emb, emb_ln_g, emb_ln_b, input_ids, attn_mask, x, xh, xl);

    const long long SS = (long long)SQ * SQ;
    const long long HSS = (long long)NHEAD * SS;
    const long long SHD = (long long)HD;
    const long long BHD = (long long)NHEAD * HD;

    for (int l = 0; l < NLAYER; l++) {
        const __nv_bfloat16 *WqTh = wth + (size_t)l*LOFF, *WqTl = wtl + (size_t)l*LOFF;
        const __nv_bfloat16 *WkTh = WqTh + WSZ,   *WkTl = WqTl + WSZ;
        const __nv_bfloat16 *WvTh = WqTh + 2*WSZ, *WvTl = WqTl + 2*WSZ;
        const __nv_bfloat16 *WoTh = WqTh + 3*WSZ, *WoTl = WqTl + 3*WSZ;
        const __nv_bfloat16 *WiTh = WqTh + 4*WSZ, *WiTl = WqTl + 4*WSZ;
        const __nv_bfloat16 *W2Th = WqTh + 4*WSZ + WISZ, *W2Tl = WqTl + 4*WSZ + WISZ;
        const float *bq_l = bq + (size_t)l*HID, *bk_l = bk + (size_t)l*HID, *bv_l = bv + (size_t)l*HID;
        const float *bo_l = bo + (size_t)l*HID, *bi_l = bi + (size_t)l*FFDIM, *bo2_l = bo2 + (size_t)l*HID;

        tmma(xh, xl, WqTh, WqTl, bq_l, nullptr, nullptr, qh, ql,
             ROWS, HID, HID, HID, HID, 0, 0, 0,0,0,0, 0,0,0,0, 1, 1, FL_HSC);
        tmma(xh, xl, WkTh, WkTl, bk_l, nullptr, nullptr, kh, kl,
             ROWS, HID, HID, HID, HID, 0, 0, 0,0,0,0, 0,0,0,0, 1, 1, FL_HSC);
        tmma(xh, xl, WvTh, WvTl, bv_l, nullptr, nullptr, vth, vtl,
             ROWS, HID, HID, HID, HID, 0, 0, 0,0,0,0, 0,0,0,0, 1, 1, FL_VT);
        tmma(relh, rell, WkTh, WkTl, bk_l, nullptr, nullptr, pkh, pkl,
             SQ, HID, HID, HID, HID, 0, 0, 0,0,0,0, 0,0,0,0, 1, 1, FL_HSC);
        tmma(relh, rell, WqTh, WqTl, bq_l, nullptr, nullptr, pqh, pql,
             SQ, HID, HID, HID, HID, 0, 0, 0,0,0,0, 0,0,0,0, 1, 1, FL_HSC);

        tmma(qh, ql, kh, kl, nullptr, nullptr, sc, nullptr, nullptr,
             SQ, SQ, DHEAD, DHEAD, DHEAD, SQ, 0,
             BHD, SHD, BHD, SHD, HSS, SS, 0, 0, NHEAD, BHT, FL_F32);
        tmma(qh, ql, pkh, pkl, nullptr, nullptr, c2p, nullptr, nullptr,
             SQ, SQ, DHEAD, DHEAD, DHEAD, SQ, 0,
             BHD, SHD, 0, SHD, HSS, SS, 0, 0, NHEAD, BHT, FL_F32);
        tmma(kh, kl, pqh, pql, nullptr, nullptr, p2c, nullptr, nullptr,
             SQ, SQ, DHEAD, DHEAD, DHEAD, SQ, 0,
             BHD, SHD, 0, SHD, HSS, SS, 0, 0, NHEAD, BHT, FL_F32);

        attn_softmax_kernel<<<dim3(SQ, BHT), 256>>>(sc, c2p, p2c, attn_mask, ph, pl);

        tmma(ph, pl, vth, vtl, nullptr, nullptr, nullptr, ctxh, ctxl,
             SQ, DHEAD, SQ, SQ, SQ, 0, HID,
             HSS, SS, BHD, SHD, 0, 0, (long long)SQ*HID, DHEAD, NHEAD, BHT, FL_HILO);

        tmma(ctxh, ctxl, WoTh, WoTl, bo_l, x, tmp, nullptr, nullptr,
             ROWS, HID, HID, HID, HID, HID, 0, 0,0,0,0, 0,0,0,0, 1, 1, FL_F32 | FL_RES);
        ln_kernel<<<ROWS, 256>>>(tmp, ln1_g + (size_t)l*HID, ln1_b + (size_t)l*HID, h1, h1h, h1l);

        tmma(h1h, h1l, WiTh, WiTl, bi_l, nullptr, nullptr, ffh, ffl,
             ROWS, FFDIM, HID, HID, HID, 0, FFDIM, 0,0,0,0, 0,0,0,0, 1, 1, FL_GELU | FL_HILO);
        tmma(ffh, ffl, W2Th, W2Tl, bo2_l, h1, tmp, nullptr, nullptr,
             ROWS, HID, FFDIM, FFDIM, FFDIM, HID, 0, 0,0,0,0, 0,0,0,0, 1, 1, FL_F32 | FL_RES);
        ln_kernel<<<ROWS, 256>>>(tmp, ln2_g + (size_t)l*HID, ln2_b + (size_t)l*HID,
                                 (l == NLAYER - 1) ? out : x,
                                 (l == NLAYER - 1) ? nullptr : xh,
                                 (l == NLAYER - 1) ? nullptr : xl);
    }
}

// round 9
// speedup vs baseline: 2.4814x; 1.0005x over previous
#include <cuda_runtime.h>
#include <cuda_bf16.h>
#include <math.h>
#include <stdint.h>

#define SQ 512
#define HID 768
#define NHEAD 12
#define DHEAD 64
#define BATCH 8
#define NLAYER 12
#define FFDIM 3072
#define ROWS (BATCH*SQ)
#define BHT (BATCH*NHEAD)
#define HD (SQ*DHEAD)

#define WSZ (HID*HID)
#define WISZ (HID*FFDIM)
#define LOFF (4*WSZ + 2*WISZ)

/* ------------------------- scratch (device globals) ---------------------- */
__device__ float g_x[ROWS*HID];
__device__ float g_h1[ROWS*HID];
__device__ float g_tmp[ROWS*HID];
__device__ __nv_bfloat16 g_xh[ROWS*HID],  g_xl[ROWS*HID];
__device__ __nv_bfloat16 g_h1h[ROWS*HID], g_h1l[ROWS*HID];
__device__ __nv_bfloat16 g_qh[ROWS*HID],  g_ql[ROWS*HID];
__device__ __nv_bfloat16 g_kh[ROWS*HID],  g_kl[ROWS*HID];
__device__ __nv_bfloat16 g_vth[ROWS*HID], g_vtl[ROWS*HID];
__device__ __nv_bfloat16 g_ctxh[ROWS*HID],g_ctxl[ROWS*HID];
__device__ __nv_bfloat16 g_ffh[(size_t)ROWS*FFDIM], g_ffl[(size_t)ROWS*FFDIM];
__device__ __nv_bfloat16 g_pkh[NHEAD*HD], g_pkl[NHEAD*HD];
__device__ __nv_bfloat16 g_pqh[NHEAD*HD], g_pql[NHEAD*HD];
__device__ __nv_bfloat16 g_relh[SQ*HID],  g_rell[SQ*HID];
__device__ __nv_bfloat16 g_wth[(size_t)NLAYER*LOFF];
__device__ __nv_bfloat16 g_wtl[(size_t)NLAYER*LOFF];
__device__ float g_sc[(size_t)BHT*SQ*SQ];
__device__ float g_c2p[(size_t)BHT*SQ*SQ];
__device__ float g_p2c[(size_t)BHT*SQ*SQ];
__device__ __nv_bfloat16 g_ph[(size_t)BHT*SQ*SQ], g_pl[(size_t)BHT*SQ*SQ];
__device__ int g_cidx[1023], g_pidx[1023];

/* ------------------------- PTX helpers ----------------------------------- */
__device__ __forceinline__ uint32_t smem_u32(const void* p) {
    uint32_t a;
    asm("{ .reg .u64 t; cvta.to.shared.u64 t, %1; cvt.u32.u64 %0, t; }" : "=r"(a) : "l"(p));
    return a;
}
#define SWZ(x) ((x) ^ (((x) >> 3) & 0x70))

#define CPA16(dst, src) asm volatile("cp.async.cg.shared.global [%0], [%1], 16;" :: "r"(dst), "l"(src))
#define CPA_COMMIT() asm volatile("cp.async.commit_group;" ::: "memory")
#define CPA_WAIT1() asm volatile("cp.async.wait_group 1;" ::: "memory")
#define CPA_WAIT0() asm volatile("cp.async.wait_group 0;" ::: "memory")

__device__ __forceinline__ void ldm4(uint32_t* r, uint32_t addr) {
    asm volatile("ldmatrix.sync.aligned.m8n8.x4.shared.b16 {%0,%1,%2,%3}, [%4];"
        : "=r"(r[0]), "=r"(r[1]), "=r"(r[2]), "=r"(r[3]) : "r"(addr));
}
__device__ __forceinline__ void mma16816(float* c, const uint32_t* a, uint32_t b0, uint32_t b1) {
    asm volatile("mma.sync.aligned.m16n8k16.row.col.f32.bf16.bf16.f32 "
        "{%0,%1,%2,%3}, {%4,%5,%6,%7}, {%8,%9}, {%0,%1,%2,%3};"
        : "+f"(c[0]), "+f"(c[1]), "+f"(c[2]), "+f"(c[3])
        : "r"(a[0]), "r"(a[1]), "r"(a[2]), "r"(a[3]), "r"(b0), "r"(b1));
}
__device__ __forceinline__ uint32_t amat_addr(uint32_t base, int mbase, int ks, int lane) {
    int mat = lane >> 3, rin = lane & 7;
    int m = mbase + rin + ((mat & 1) << 3);
    int quad = 2 * ks + (mat >> 1);
    return base + SWZ(m * 128 + quad * 16);
}
__device__ __forceinline__ uint32_t bmat_addr(uint32_t base, int nbase, int ks, int lane) {
    int mat = lane >> 3, rin = lane & 7;
    int n = nbase + rin + ((mat >> 1) << 3);
    int quad = 2 * ks + (mat & 1);
    return base + SWZ(n * 128 + quad * 16);
}

/* ------------------------- rel-pos bucket tables -------------------------- */
__device__ __forceinline__ int log_bucket(int rel) {
    const int mid = 128;
    float abs_pos;
    if (rel < mid && rel > -mid) abs_pos = (float)(mid - 1);
    else                         abs_pos = fabsf((float)rel);
    if (abs_pos <= (float)mid) return rel;
    float denom = (float)log(511.0 / 128.0);
    float log_pos = ceilf(logf(abs_pos / 128.0f) / denom * 127.0f) + 128.0f;
    float sgn = (rel > 0) ? 1.0f : ((rel < 0) ? -1.0f : 0.0f);
    return (int)(log_pos * sgn);
}
__global__ void build_tables_kernel() {
    int i = blockIdx.x * blockDim.x + threadIdx.x;
    if (i >= 1023) return;
    int d = i - 511;
    int c = log_bucket(d) + 256;  c = min(max(c, 0), 511);
    int p = 256 - log_bucket(-d); p = min(max(p, 0), 511);
    g_cidx[i] = c; g_pidx[i] = p;
}

__device__ __forceinline__ void split1(float v, __nv_bfloat16& h, __nv_bfloat16& l) {
    h = __float2bfloat16(v);
    l = __float2bfloat16(v - __bfloat162float(h));
}

/* transpose + hi/lo split: dst[n*K+k] = split(src[k*N+n]) */
__global__ void wsplit_kernel(const float* __restrict__ src, __nv_bfloat16* __restrict__ dh,
                              __nv_bfloat16* __restrict__ dl, int K, int N,
                              long long sStride, long long dStride) {
    __shared__ float t[32][33];
    int l = blockIdx.z;
    const float* s = src + (size_t)l * sStride;
    __nv_bfloat16* oh = dh + (size_t)l * dStride;
    __nv_bfloat16* ol = dl + (size_t)l * dStride;
    int k0 = blockIdx.x * 32, n0 = blockIdx.y * 32;
    int tx = threadIdx.x, ty = threadIdx.y;
#pragma unroll
    for (int i = 0; i < 32; i += 8) t[ty + i][tx] = s[(size_t)(k0 + ty + i) * N + n0 + tx];
    __syncthreads();
#pragma unroll
    for (int i = 0; i < 32; i += 8) {
        float v = t[tx][ty + i];
        __nv_bfloat16 h, lo; split1(v, h, lo);
        size_t o = (size_t)(n0 + ty + i) * K + k0 + tx;
        oh[o] = h; ol[o] = lo;
    }
}

__global__ void split_kernel(const float* __restrict__ s, __nv_bfloat16* __restrict__ oh,
                             __nv_bfloat16* __restrict__ ol, int n) {
    int i = blockIdx.x * blockDim.x + threadIdx.x;
    if (i < n) { __nv_bfloat16 h, l; split1(s[i], h, l); oh[i] = h; ol[i] = l; }
}

/* ------------------------- embedding + masked LN -------------------------- */
__global__ void embed_kernel(const float* __restrict__ we, const float* __restrict__ pe,
                             const float* __restrict__ lg, const float* __restrict__ lb,
                             const int* __restrict__ ids, const int* __restrict__ am,
                             float* __restrict__ out, __nv_bfloat16* __restrict__ outh,
                             __nv_bfloat16* __restrict__ outl) {
    __shared__ float red[256];
    int row = blockIdx.x, tid = threadIdx.x;
    int s = row & (SQ - 1);
    int id = ids[row];
    float v[3];
#pragma unroll
    for (int i = 0; i < 3; i++) {
        int c = tid + i * 256;
        v[i] = we[(size_t)id * HID + c] + pe[(size_t)s * HID + c];
    }
    float sum = v[0] + v[1] + v[2];
    red[tid] = sum; __syncthreads();
    for (int st = 128; st > 0; st >>= 1) { if (tid < st) red[tid] += red[tid + st]; __syncthreads(); }
    float mu = red[0] * (1.0f / HID); __syncthreads();
    float s2 = 0.f;
#pragma unroll
    for (int i = 0; i < 3; i++) { float d = v[i] - mu; s2 += d * d; }
    red[tid] = s2; __syncthreads();
    for (int st = 128; st > 0; st >>= 1) { if (tid < st) red[tid] += red[tid + st]; __syncthreads(); }
    float r = rsqrtf(red[0] * (1.0f / HID) + 1e-7f);
    float mf = (float)am[row];
    size_t rb = (size_t)row * HID;
#pragma unroll
    for (int i = 0; i < 3; i++) {
        int c = tid + i * 256;
        float o = ((v[i] - mu) * r * lg[c] + lb[c]) * mf;
        out[rb + c] = o;
        __nv_bfloat16 h, l; split1(o, h, l);
        outh[rb + c] = h; outl[rb + c] = l;
    }
}

/* ------------------------- layernorm (+ optional hi/lo) ------------------- */
__global__ void ln_kernel(const float* __restrict__ in, const float* __restrict__ lg,
                          const float* __restrict__ lb, float* __restrict__ out,
                          __nv_bfloat16* __restrict__ outh, __nv_bfloat16* __restrict__ outl) {
    __shared__ float red[256];
    int row = blockIdx.x, tid = threadIdx.x;
    const float* xr = in + (size_t)row * HID;
    float v[3];
#pragma unroll
    for (int i = 0; i < 3; i++) v[i] = xr[tid + i * 256];
    float sum = v[0] + v[1] + v[2];
    red[tid] = sum; __syncthreads();
    for (int st = 128; st > 0; st >>= 1) { if (tid < st) red[tid] += red[tid + st]; __syncthreads(); }
    float mu = red[0] * (1.0f / HID); __syncthreads();
    float s2 = 0.f;
#pragma unroll
    for (int i = 0; i < 3; i++) { float d = v[i] - mu; s2 += d * d; }
    red[tid] = s2; __syncthreads();
    for (int st = 128; st > 0; st >>= 1) { if (tid < st) red[tid] += red[tid + st]; __syncthreads(); }
    float r = rsqrtf(red[0] * (1.0f / HID) + 1e-7f);
    size_t rb = (size_t)row * HID;
#pragma unroll
    for (int i = 0; i < 3; i++) {
        int c = tid + i * 256;
        float o = (v[i] - mu) * r * lg[c] + lb[c];
        out[rb + c] = o;
        if (outh) { __nv_bfloat16 h, l; split1(o, h, l); outh[rb + c] = h; outl[rb + c] = l; }
    }
}

/* ------------------------- softmax (gather + mask -> bf16 hi/lo) ---------- */
__global__ void attn_softmax_kernel(const float* __restrict__ sc, const float* __restrict__ c2p,
                                    const float* __restrict__ p2c, const int* __restrict__ am,
                                    __nv_bfloat16* __restrict__ ph, __nv_bfloat16* __restrict__ pl) {
    int q = blockIdx.x, bh = blockIdx.y;
    int b = bh / NHEAD;
    const float inv_scale = 0.07216878364870322f;
    const float* row  = sc  + ((size_t)bh * SQ + q) * SQ;
    const float* crow = c2p + ((size_t)bh * SQ + q) * SQ;
    const float* pbh  = p2c + (size_t)bh * SQ * SQ;
    int tid = threadIdx.x;
    bool mq = am[b * SQ + q] != 0;

    float v[2]; bool ok[2];
    float lmax = -3.402823466e38f;
#pragma unroll
    for (int i = 0; i < 2; i++) {
        int k = tid + i * 256;
        int di = q - k + 511;
        float s = (row[k] + crow[g_cidx[di]] + pbh[(size_t)k * SQ + g_pidx[di]]) * inv_scale;
        ok[i] = mq && (am[b * SQ + k] != 0);
        v[i] = ok[i] ? s : -3.402823466e38f;
        lmax = fmaxf(lmax, v[i]);
    }
    __shared__ float red[256];
    red[tid] = lmax; __syncthreads();
    for (int st = 128; st > 0; st >>= 1) { if (tid < st) red[tid] = fmaxf(red[tid], red[tid + st]); __syncthreads(); }
    float m = red[0]; __syncthreads();
    float ls = 0.f;
#pragma unroll
    for (int i = 0; i < 2; i++) { float e = expf(v[i] - m); v[i] = e; ls += e; }
    red[tid] = ls; __syncthreads();
    for (int st = 128; st > 0; st >>= 1) { if (tid < st) red[tid] += red[tid + st]; __syncthreads(); }
    float inv = 1.0f / red[0];
    size_t ob = ((size_t)bh * SQ + q) * SQ;
#pragma unroll
    for (int i = 0; i < 2; i++) {
        int k = tid + i * 256;
        float p = ok[i] ? v[i] * inv : 0.0f;
        __nv_bfloat16 h, l; split1(p, h, l);
        ph[ob + k] = h; pl[ob + k] = l;
    }
}

/* ------------------------- mma.sync split-bf16 GEMM (2-stage pipe) -------- */
#define KC 64
#define ABYTES 16384   /* 128 rows x 128B */

#define FL_GELU 1
#define FL_RES  2
#define FL_F32  4
#define FL_HILO 8
#define FL_HSC  16
#define FL_VT   32

__device__ __forceinline__ void epi_pair(
    float v0, float v1, int m, int n,
    const float* bias, const float* Rb, float* Cf,
    __nv_bfloat16* Chi, __nv_bfloat16* Clo,
    int ldc, int ldh, size_t cfoff, size_t hoff, int flags)
{
    if (bias) { v0 += __ldg(bias + n); v1 += __ldg(bias + n + 1); }
    if (flags & FL_RES) {
        float2 rv = *reinterpret_cast<const float2*>(Rb + (size_t)m * ldc + n);
        v0 += rv.x; v1 += rv.y;
    }
    if (flags & FL_GELU) {
        v0 = 0.5f * v0 * (1.0f + erff(v0 * 0.70710678118654752f));
        v1 = 0.5f * v1 * (1.0f + erff(v1 * 0.70710678118654752f));
    }
    if (flags & FL_F32) {
        float2* p = reinterpret_cast<float2*>(Cf + cfoff + (size_t)m * ldc + n);
        *p = make_float2(v0, v1);
    }
    if (flags & (FL_HILO | FL_HSC)) {
        size_t base;
        if (flags & FL_HSC)
            base = (size_t)(m >> 9) * ((size_t)NHEAD * HD) + (size_t)(n >> 6) * HD
                 + (size_t)(m & 511) * 64 + (n & 63);
        else
            base = hoff + (size_t)m * ldh + n;
        __nv_bfloat16 h0, l0, h1, l1;
        split1(v0, h0, l0); split1(v1, h1, l1);
        __nv_bfloat162 hh; hh.x = h0; hh.y = h1;
        __nv_bfloat162 ll; ll.x = l0; ll.y = l1;
        *reinterpret_cast<uint32_t*>(Chi + base) = *reinterpret_cast<uint32_t*>(&hh);
        *reinterpret_cast<uint32_t*>(Clo + base) = *reinterpret_cast<uint32_t*>(&ll);
    }
    if (flags & FL_VT) {
        size_t i0 = ((size_t)(m >> 9) * NHEAD + (n >> 6)) * ((size_t)64 * SQ)
                  + (size_t)(n & 63) * SQ + (m & 511);
        size_t i1 = ((size_t)(m >> 9) * NHEAD + ((n + 1) >> 6)) * ((size_t)64 * SQ)
                  + (size_t)((n + 1) & 63) * SQ + (m & 511);
        __nv_bfloat16 h, l;
        split1(v0, h, l); Chi[i0] = h; Clo[i0] = l;
        split1(v1, h, l); Chi[i1] = h; Clo[i1] = l;
    }
}

template<int TN>
__device__ __forceinline__ void load_chunk(
    uint32_t sst, const __nv_bfloat16* Azh, const __nv_bfloat16* Azl,
    const __nv_bfloat16* Bzh, const __nv_bfloat16* Bzl,
    int m0, int n0, int k0, int lda, int ldb, int tid)
{
    const uint32_t oAl = ABYTES, oBh = 2 * ABYTES, oBl = 2 * ABYTES + TN * 128;
#pragma unroll
    for (int i = 0; i < 4; i++) {
        int q = tid + i * 256;
        int row = q >> 3, quad = q & 7;
        size_t goff = (size_t)(m0 + row) * lda + k0 + quad * 8;
        uint32_t so = SWZ(row * 128 + quad * 16);
        CPA16(sst + so, Azh + goff);
        CPA16(sst + oAl + so, Azl + goff);
    }
#pragma unroll
    for (int i = 0; i < TN / 32; i++) {
        int q = tid + i * 256;
        int row = q >> 3, quad = q & 7;
        size_t goff = (size_t)(n0 + row) * ldb + k0 + quad * 8;
        uint32_t so = SWZ(row * 128 + quad * 16);
        CPA16(sst + oBh + so, Bzh + goff);
        CPA16(sst + oBl + so, Bzl + goff);
    }
    CPA_COMMIT();
}

template<int TN>
__global__ __launch_bounds__(256)
void hmma_kernel(const __nv_bfloat16* __restrict__ Ah, const __nv_bfloat16* __restrict__ Al,
                 const __nv_bfloat16* __restrict__ Bh, const __nv_bfloat16* __restrict__ Bl,
                 const float* __restrict__ bias, const float* __restrict__ Rb,
                 float* __restrict__ Cf, __nv_bfloat16* __restrict__ Chi, __nv_bfloat16* __restrict__ Clo,
                 int K, int lda, int ldb, int ldc, int ldh,
                 long long sAb, long long sAh_, long long sBb, long long sBh_,
                 long long sCb, long long sCh_, long long sHb, long long sHh_,
                 int nh, int flags)
{
    extern __shared__ char smem[];
    const int STAGE = 2 * ABYTES + 2 * TN * 128;
    uint32_t sb = smem_u32(smem);

    int tid = threadIdx.x, wid = tid >> 5, lane = tid & 31;
    int z = blockIdx.z, bo = z / nh, ho = z - bo * nh;
    int m0 = blockIdx.y * 128, n0 = blockIdx.x * TN;

    const __nv_bfloat16* Azh = Ah + (size_t)bo * sAb + (size_t)ho * sAh_;
    const __nv_bfloat16* Azl = Al + (size_t)bo * sAb + (size_t)ho * sAh_;
    const __nv_bfloat16* Bzh = Bh + (size_t)bo * sBb + (size_t)ho * sBh_;
    const __nv_bfloat16* Bzl = Bl + (size_t)bo * sBb + (size_t)ho * sBh_;

    const int MI = (TN == 128) ? 2 : 1;
    int wm = (TN == 128) ? (wid & 3) * 32 : wid * 16;
    int wn = (TN == 128) ? (wid >> 2) * 64 : 0;

    float acc[(TN == 128) ? 2 : 1][8][4];
#pragma unroll
    for (int a = 0; a < MI; a++)
#pragma unroll
        for (int b = 0; b < 8; b++)
#pragma unroll
            for (int c = 0; c < 4; c++) acc[a][b][c] = 0.f;

    int nch = K / KC;
    load_chunk<TN>(sb, Azh, Azl, Bzh, Bzl, m0, n0, 0, lda, ldb, tid);

    for (int ch = 0; ch < nch; ch++) {
        if (ch + 1 < nch) {
            load_chunk<TN>(sb + ((ch + 1) & 1) * STAGE, Azh, Azl, Bzh, Bzl,
                           m0, n0, (ch + 1) * KC, lda, ldb, tid);
            CPA_WAIT1();
        } else {
            CPA_WAIT0();
        }
        __syncthreads();

        uint32_t st = sb + (ch & 1) * STAGE;
        const uint32_t oAl = ABYTES, oBh = 2 * ABYTES, oBl = 2 * ABYTES + TN * 128;
#pragma unroll
        for (int ks = 0; ks < 4; ks++) {
            uint32_t ah[MI][4], al[MI][4];
#pragma unroll
            for (int mi = 0; mi < MI; mi++) {
                ldm4(ah[mi], amat_addr(st, wm + mi * 16, ks, lane));
                ldm4(al[mi], amat_addr(st + oAl, wm + mi * 16, ks, lane));
            }
            /* process ng in pairs; within each product pass all accumulators
               are distinct -> same-acc reuse distance is 8 mmas, not 1 */
#pragma unroll
            for (int ngp = 0; ngp < 4; ngp += 2) {
                uint32_t b0h[4], b1h[4], b0l[4], b1l[4];
                ldm4(b0h, bmat_addr(st + oBh, wn + ngp * 16, ks, lane));
                ldm4(b1h, bmat_addr(st + oBh, wn + (ngp + 1) * 16, ks, lane));
                ldm4(b0l, bmat_addr(st + oBl, wn + ngp * 16, ks, lane));
                ldm4(b1l, bmat_addr(st + oBl, wn + (ngp + 1) * 16, ks, lane));
#pragma unroll
                for (int mi = 0; mi < MI; mi++) {   /* pass 1: ah*bh */
                    mma16816(acc[mi][2 * ngp],     ah[mi], b0h[0], b0h[1]);
                    mma16816(acc[mi][2 * ngp + 1], ah[mi], b0h[2], b0h[3]);
                    mma16816(acc[mi][2 * ngp + 2], ah[mi], b1h[0], b1h[1]);
                    mma16816(acc[mi][2 * ngp + 3], ah[mi], b1h[2], b1h[3]);
                }
#pragma unroll
                for (int mi = 0; mi < MI; mi++) {   /* pass 2: ah*bl */
                    mma16816(acc[mi][2 * ngp],     ah[mi], b0l[0], b0l[1]);
                    mma16816(acc[mi][2 * ngp + 1], ah[mi], b0l[2], b0l[3]);
                    mma16816(acc[mi][2 * ngp + 2], ah[mi], b1l[0], b1l[1]);
                    mma16816(acc[mi][2 * ngp + 3], ah[mi], b1l[2], b1l[3]);
                }
#pragma unroll
                for (int mi = 0; mi < MI; mi++) {   /* pass 3: al*bh */
                    mma16816(acc[mi][2 * ngp],     al[mi], b0h[0], b0h[1]);
                    mma16816(acc[mi][2 * ngp + 1], al[mi], b0h[2], b0h[3]);
                    mma16816(acc[mi][2 * ngp + 2], al[mi], b1h[0], b1h[1]);
                    mma16816(acc[mi][2 * ngp + 3], al[mi], b1h[2], b1h[3]);
                }
            }
        }
        __syncthreads();
    }

    size_t cfoff = (size_t)bo * sCb + (size_t)ho * sCh_;
    size_t hoff  = (size_t)bo * sHb + (size_t)ho * sHh_;
    int r0 = lane >> 2, cc = (lane & 3) * 2;
#pragma unroll
    for (int mi = 0; mi < MI; mi++) {
#pragma unroll
        for (int nf = 0; nf < 8; nf++) {
            int m_ = m0 + wm + mi * 16 + r0;
            int n_ = n0 + wn + nf * 8 + cc;
            epi_pair(acc[mi][nf][0], acc[mi][nf][1], m_,     n_, bias, Rb, Cf, Chi, Clo, ldc, ldh, cfoff, hoff, flags);
            epi_pair(acc[mi][nf][2], acc[mi][nf][3], m_ + 8, n_, bias, Rb, Cf, Chi, Clo, ldc, ldh, cfoff, hoff, flags);
        }
    }
}

/* ------------------------- host-side GEMM wrapper ------------------------- */
#define STAGE128 (2 * ABYTES + 2 * 128 * 128)
#define STAGE64  (2 * ABYTES + 2 * 64 * 128)

static void tmma(const __nv_bfloat16* Ah, const __nv_bfloat16* Al,
                 const __nv_bfloat16* Bh, const __nv_bfloat16* Bl,
                 const float* bias, const float* Rb,
                 float* Cf, __nv_bfloat16* Chi, __nv_bfloat16* Clo,
                 int M, int N, int K, int lda, int ldb, int ldc, int ldh,
                 long long sAb, long long sAh, long long sBb, long long sBh,
                 long long sCb, long long sCh, long long sHb, long long sHh,
                 int nh, int nz, int flags)
{
    int stages = (K <= KC) ? 1 : 2;   /* single chunk -> no second buffer */
    if (N >= 128) {
        dim3 g(N / 128, M / 128, nz);
        hmma_kernel<128><<<g, 256, stages * STAGE128>>>(Ah, Al, Bh, Bl, bias, Rb, Cf, Chi, Clo,
            K, lda, ldb, ldc, ldh, sAb, sAh, sBb, sBh, sCb, sCh, sHb, sHh, nh, flags);
    } else {
        dim3 g(1, M / 128, nz);
        hmma_kernel<64><<<g, 256, stages * STAGE64>>>(Ah, Al, Bh, Bl, bias, Rb, Cf, Chi, Clo,
            K, lda, ldb, ldc, ldh, sAb, sAh, sBb, sBh, sCb, sCh, sHb, sHh, nh, flags);
    }
}

extern "C" void kernel_launch(void* const* d_in, const int* in_sizes, int n_in,
                              void* d_out, int out_size) {
    const float* word_emb = (const float*)d_in[0];
    const float* pos_emb  = (const float*)d_in[1];
    const float* emb_ln_g = (const float*)d_in[2];
    const float* emb_ln_b = (const float*)d_in[3];
    const float* rel_emb  = (const float*)d_in[4];
    const float* Wq = (const float*)d_in[5];
    const float* bq = (const float*)d_in[6];
    const float* Wk = (const float*)d_in[7];
    const float* bk = (const float*)d_in[8];
    const float* Wv = (const float*)d_in[9];
    const float* bv = (const float*)d_in[10];
    const float* Wo = (const float*)d_in[11];
    const float* bo = (const float*)d_in[12];
    const float* ln1_g = (const float*)d_in[13];
    const float* ln1_b = (const float*)d_in[14];
    const float* Wi = (const float*)d_in[15];
    const float* bi = (const float*)d_in[16];
    const float* Wo2 = (const float*)d_in[17];
    const float* bo2 = (const float*)d_in[18];
    const float* ln2_g = (const float*)d_in[19];
    const float* ln2_b = (const float*)d_in[20];
    const int* input_ids = (const int*)d_in[21];
    const int* attn_mask = (const int*)d_in[22];
    float* out = (float*)d_out;

    cudaFuncSetAttribute(hmma_kernel<128>, cudaFuncAttributeMaxDynamicSharedMemorySize, 2 * STAGE128);
    cudaFuncSetAttribute(hmma_kernel<64>,  cudaFuncAttributeMaxDynamicSharedMemorySize, 2 * STAGE64);

    float *x, *h1, *tmp, *sc, *c2p, *p2c;
    __nv_bfloat16 *xh, *xl, *h1h, *h1l, *qh, *ql, *kh, *kl, *vth, *vtl, *ctxh, *ctxl;
    __nv_bfloat16 *ffh, *ffl, *pkh, *pkl, *pqh, *pql, *relh, *rell, *wth, *wtl, *ph, *pl;
    cudaGetSymbolAddress((void**)&x, g_x);       cudaGetSymbolAddress((void**)&h1, g_h1);
    cudaGetSymbolAddress((void**)&tmp, g_tmp);
    cudaGetSymbolAddress((void**)&sc, g_sc);     cudaGetSymbolAddress((void**)&c2p, g_c2p);
    cudaGetSymbolAddress((void**)&p2c, g_p2c);
    cudaGetSymbolAddress((void**)&xh, g_xh);     cudaGetSymbolAddress((void**)&xl, g_xl);
    cudaGetSymbolAddress((void**)&h1h, g_h1h);   cudaGetSymbolAddress((void**)&h1l, g_h1l);
    cudaGetSymbolAddress((void**)&qh, g_qh);     cudaGetSymbolAddress((void**)&ql, g_ql);
    cudaGetSymbolAddress((void**)&kh, g_kh);     cudaGetSymbolAddress((void**)&kl, g_kl);
    cudaGetSymbolAddress((void**)&vth, g_vth);   cudaGetSymbolAddress((void**)&vtl, g_vtl);
    cudaGetSymbolAddress((void**)&ctxh, g_ctxh); cudaGetSymbolAddress((void**)&ctxl, g_ctxl);
    cudaGetSymbolAddress((void**)&ffh, g_ffh);   cudaGetSymbolAddress((void**)&ffl, g_ffl);
    cudaGetSymbolAddress((void**)&pkh, g_pkh);   cudaGetSymbolAddress((void**)&pkl, g_pkl);
    cudaGetSymbolAddress((void**)&pqh, g_pqh);   cudaGetSymbolAddress((void**)&pql, g_pql);
    cudaGetSymbolAddress((void**)&relh, g_relh); cudaGetSymbolAddress((void**)&rell, g_rell);
    cudaGetSymbolAddress((void**)&wth, g_wth);   cudaGetSymbolAddress((void**)&wtl, g_wtl);
    cudaGetSymbolAddress((void**)&ph, g_ph);     cudaGetSymbolAddress((void**)&pl, g_pl);

    build_tables_kernel<<<1, 1024>>>();

    dim3 tb(32, 8);
    wsplit_kernel<<<dim3(HID/32, HID/32, NLAYER), tb>>>(Wq,  wth + 0*WSZ,        wtl + 0*WSZ,        HID, HID,   (long long)WSZ,  (long long)LOFF);
    wsplit_kernel<<<dim3(HID/32, HID/32, NLAYER), tb>>>(Wk,  wth + 1*WSZ,        wtl + 1*WSZ,        HID, HID,   (long long)WSZ,  (long long)LOFF);
    wsplit_kernel<<<dim3(HID/32, HID/32, NLAYER), tb>>>(Wv,  wth + 2*WSZ,        wtl + 2*WSZ,        HID, HID,   (long long)WSZ,  (long long)LOFF);
    wsplit_kernel<<<dim3(HID/32, HID/32, NLAYER), tb>>>(Wo,  wth + 3*WSZ,        wtl + 3*WSZ,        HID, HID,   (long long)WSZ,  (long long)LOFF);
    wsplit_kernel<<<dim3(HID/32, FFDIM/32, NLAYER), tb>>>(Wi,  wth + 4*WSZ,      wtl + 4*WSZ,        HID, FFDIM, (long long)WISZ, (long long)LOFF);
    wsplit_kernel<<<dim3(FFDIM/32, HID/32, NLAYER), tb>>>(Wo2, wth + 4*WSZ+WISZ, wtl + 4*WSZ+WISZ,   FFDIM, HID, (long long)WISZ, (long long)LOFF);
    split_kernel<<<(SQ*HID + 255)/256, 256>>>(rel_emb, relh, rell, SQ*HID);

    embed_kernel<<<ROWS, 256>>>(word_emb, pos_emb, emb_ln_g, emb_ln_b, input_ids, attn_mask, x, xh, xl);

    const long long SS = (long long)SQ * SQ;
    const long long HSS = (long long)NHEAD * SS;
    const long long SHD = (long long)HD;
    const long long BHD = (long long)NHEAD * HD;

    for (int l = 0; l < NLAYER; l++) {
        const __nv_bfloat16 *WqTh = wth + (size_t)l*LOFF, *WqTl = wtl + (size_t)l*LOFF;
        const __nv_bfloat16 *WkTh = WqTh + WSZ,   *WkTl = WqTl + WSZ;
        const __nv_bfloat16 *WvTh = WqTh + 2*WSZ, *WvTl = WqTl + 2*WSZ;
        const __nv_bfloat16 *WoTh = WqTh + 3*WSZ, *WoTl = WqTl + 3*WSZ;
        const __nv_bfloat16 *WiTh = WqTh + 4*WSZ, *WiTl = WqTl + 4*WSZ;
        const __nv_bfloat16 *W2Th = WqTh + 4*WSZ + WISZ, *W2Tl = WqTl + 4*WSZ + WISZ;
        const float *bq_l = bq + (size_t)l*HID, *bk_l = bk + (size_t)l*HID, *bv_l = bv + (size_t)l*HID;
        const float *bo_l = bo + (size_t)l*HID, *bi_l = bi + (size_t)l*FFDIM, *bo2_l = bo2 + (size_t)l*HID;

        tmma(xh, xl, WqTh, WqTl, bq_l, nullptr, nullptr, qh, ql,
             ROWS, HID, HID, HID, HID, 0, 0, 0,0,0,0, 0,0,0,0, 1, 1, FL_HSC);
        tmma(xh, xl, WkTh, WkTl, bk_l, nullptr, nullptr, kh, kl,
             ROWS, HID, HID, HID, HID, 0, 0, 0,0,0,0, 0,0,0,0, 1, 1, FL_HSC);
        tmma(xh, xl, WvTh, WvTl, bv_l, nullptr, nullptr, vth, vtl,
             ROWS, HID, HID, HID, HID, 0, 0, 0,0,0,0, 0,0,0,0, 1, 1, FL_VT);
        tmma(relh, rell, WkTh, WkTl, bk_l, nullptr, nullptr, pkh, pkl,
             SQ, HID, HID, HID, HID, 0, 0, 0,0,0,0, 0,0,0,0, 1, 1, FL_HSC);
        tmma(relh, rell, WqTh, WqTl, bq_l, nullptr, nullptr, pqh, pql,
             SQ, HID, HID, HID, HID, 0, 0, 0,0,0,0, 0,0,0,0, 1, 1, FL_HSC);

        tmma(qh, ql, kh, kl, nullptr, nullptr, sc, nullptr, nullptr,
             SQ, SQ, DHEAD, DHEAD, DHEAD, SQ, 0,
             BHD, SHD, BHD, SHD, HSS, SS, 0, 0, NHEAD, BHT, FL_F32);
        tmma(qh, ql, pkh, pkl, nullptr, nullptr, c2p, nullptr, nullptr,
             SQ, SQ, DHEAD, DHEAD, DHEAD, SQ, 0,
             BHD, SHD, 0, SHD, HSS, SS, 0, 0, NHEAD, BHT, FL_F32);
        tmma(kh, kl, pqh, pql, nullptr, nullptr, p2c, nullptr, nullptr,
             SQ, SQ, DHEAD, DHEAD, DHEAD, SQ, 0,
             BHD, SHD, 0, SHD, HSS, SS, 0, 0, NHEAD, BHT, FL_F32);

        attn_softmax_kernel<<<dim3(SQ, BHT), 256>>>(sc, c2p, p2c, attn_mask, ph, pl);

        tmma(ph, pl, vth, vtl, nullptr, nullptr, nullptr, ctxh, ctxl,
             SQ, DHEAD, SQ, SQ, SQ, 0, HID,
             HSS, SS, BHD, SHD, 0, 0, (long long)SQ*HID, DHEAD, NHEAD, BHT, FL_HILO);

        tmma(ctxh, ctxl, WoTh, WoTl, bo_l, x, tmp, nullptr, nullptr,
             ROWS, HID, HID, HID, HID, HID, 0, 0,0,0,0, 0,0,0,0, 1, 1, FL_F32 | FL_RES);
        ln_kernel<<<ROWS, 256>>>(tmp, ln1_g + (size_t)l*HID, ln1_b + (size_t)l*HID, h1, h1h, h1l);

        tmma(h1h, h1l, WiTh, WiTl, bi_l, nullptr, nullptr, ffh, ffl,
             ROWS, FFDIM, HID, HID, HID, 0, FFDIM, 0,0,0,0, 0,0,0,0, 1, 1, FL_GELU | FL_HILO);
        tmma(ffh, ffl, W2Th, W2Tl, bo2_l, h1, tmp, nullptr, nullptr,
             ROWS, HID, FFDIM, FFDIM, FFDIM, HID, 0, 0,0,0,0, 0,0,0,0, 1, 1, FL_F32 | FL_RES);
        ln_kernel<<<ROWS, 256>>>(tmp, ln2_g + (size_t)l*HID, ln2_b + (size_t)l*HID,
                                 (l == NLAYER - 1) ? out : x,
                                 (l == NLAYER - 1) ? nullptr : xh,
                                 (l == NLAYER - 1) ? nullptr : xl);
    }
}

// round 10
// speedup vs baseline: 3.0255x; 1.2193x over previous
#include <cuda_runtime.h>
#include <cuda_bf16.h>
#include <math.h>
#include <stdint.h>

#define SQ 512
#define HID 768
#define NHEAD 12
#define DHEAD 64
#define BATCH 8
#define NLAYER 12
#define FFDIM 3072
#define ROWS (BATCH*SQ)
#define BHT (BATCH*NHEAD)
#define HD (SQ*DHEAD)

#define WSZ (HID*HID)
#define WISZ (HID*FFDIM)
#define LOFF (4*WSZ + 2*WISZ)

/* ------------------------- scratch (device globals) ---------------------- */
__device__ float g_x[ROWS*HID];
__device__ float g_h1[ROWS*HID];
__device__ float g_tmp[ROWS*HID];
__device__ __nv_bfloat16 g_xh[ROWS*HID],  g_xl[ROWS*HID];
__device__ __nv_bfloat16 g_h1h[ROWS*HID], g_h1l[ROWS*HID];
__device__ __nv_bfloat16 g_qkvh[(size_t)3*ROWS*HID], g_qkvl[(size_t)3*ROWS*HID];
__device__ __nv_bfloat16 g_ctxh[ROWS*HID],g_ctxl[ROWS*HID];
__device__ __nv_bfloat16 g_ffh[(size_t)ROWS*FFDIM], g_ffl[(size_t)ROWS*FFDIM];
__device__ __nv_bfloat16 g_pqkh[2*NHEAD*HD], g_pqkl[2*NHEAD*HD];
__device__ __nv_bfloat16 g_relh[SQ*HID],  g_rell[SQ*HID];
__device__ __nv_bfloat16 g_wth[(size_t)NLAYER*LOFF];
__device__ __nv_bfloat16 g_wtl[(size_t)NLAYER*LOFF];
__device__ float g_qkvb[NLAYER*2304];
__device__ float g_sc[(size_t)BHT*SQ*SQ];
__device__ float g_c2p[(size_t)BHT*SQ*SQ];
__device__ float g_p2c[(size_t)BHT*SQ*SQ];
__device__ __nv_bfloat16 g_ph[(size_t)BHT*SQ*SQ], g_pl[(size_t)BHT*SQ*SQ];
__device__ int g_cidx[1023], g_pidx[1023];

/* ------------------------- PTX helpers ----------------------------------- */
__device__ __forceinline__ uint32_t smem_u32(const void* p) {
    uint32_t a;
    asm("{ .reg .u64 t; cvta.to.shared.u64 t, %1; cvt.u32.u64 %0, t; }" : "=r"(a) : "l"(p));
    return a;
}
#define SWZ(x) ((x) ^ (((x) >> 3) & 0x70))

#define CPA16(dst, src) asm volatile("cp.async.cg.shared.global [%0], [%1], 16;" :: "r"(dst), "l"(src))
#define CPA_COMMIT() asm volatile("cp.async.commit_group;" ::: "memory")
#define CPA_WAIT1() asm volatile("cp.async.wait_group 1;" ::: "memory")
#define CPA_WAIT0() asm volatile("cp.async.wait_group 0;" ::: "memory")

__device__ __forceinline__ void ldm4(uint32_t* r, uint32_t addr) {
    asm volatile("ldmatrix.sync.aligned.m8n8.x4.shared.b16 {%0,%1,%2,%3}, [%4];"
        : "=r"(r[0]), "=r"(r[1]), "=r"(r[2]), "=r"(r[3]) : "r"(addr));
}
__device__ __forceinline__ void mma16816(float* c, const uint32_t* a, uint32_t b0, uint32_t b1) {
    asm volatile("mma.sync.aligned.m16n8k16.row.col.f32.bf16.bf16.f32 "
        "{%0,%1,%2,%3}, {%4,%5,%6,%7}, {%8,%9}, {%0,%1,%2,%3};"
        : "+f"(c[0]), "+f"(c[1]), "+f"(c[2]), "+f"(c[3])
        : "r"(a[0]), "r"(a[1]), "r"(a[2]), "r"(a[3]), "r"(b0), "r"(b1));
}
__device__ __forceinline__ uint32_t amat_addr(uint32_t base, int mbase, int ks, int lane) {
    int mat = lane >> 3, rin = lane & 7;
    int m = mbase + rin + ((mat & 1) << 3);
    int quad = 2 * ks + (mat >> 1);
    return base + SWZ(m * 128 + quad * 16);
}
__device__ __forceinline__ uint32_t bmat_addr(uint32_t base, int nbase, int ks, int lane) {
    int mat = lane >> 3, rin = lane & 7;
    int n = nbase + rin + ((mat >> 1) << 3);
    int quad = 2 * ks + (mat & 1);
    return base + SWZ(n * 128 + quad * 16);
}

/* ------------------------- rel-pos bucket tables -------------------------- */
__device__ __forceinline__ int log_bucket(int rel) {
    const int mid = 128;
    float abs_pos;
    if (rel < mid && rel > -mid) abs_pos = (float)(mid - 1);
    else                         abs_pos = fabsf((float)rel);
    if (abs_pos <= (float)mid) return rel;
    float denom = (float)log(511.0 / 128.0);
    float log_pos = ceilf(logf(abs_pos / 128.0f) / denom * 127.0f) + 128.0f;
    float sgn = (rel > 0) ? 1.0f : ((rel < 0) ? -1.0f : 0.0f);
    return (int)(log_pos * sgn);
}
__global__ void build_tables_kernel() {
    int i = blockIdx.x * blockDim.x + threadIdx.x;
    if (i >= 1023) return;
    int d = i - 511;
    int c = log_bucket(d) + 256;  c = min(max(c, 0), 511);
    int p = 256 - log_bucket(-d); p = min(max(p, 0), 511);
    g_cidx[i] = c; g_pidx[i] = p;
}

__device__ __forceinline__ void split1(float v, __nv_bfloat16& h, __nv_bfloat16& l) {
    h = __float2bfloat16(v);
    l = __float2bfloat16(v - __bfloat162float(h));
}

/* staged concat bias [L][2304] = [bq|bk|bv] */
__global__ void qkvbias_kernel(const float* __restrict__ bq, const float* __restrict__ bk,
                               const float* __restrict__ bv, float* __restrict__ out) {
    int i = blockIdx.x * blockDim.x + threadIdx.x;
    if (i >= NLAYER * 2304) return;
    int l = i / 2304, j = i - l * 2304;
    float v;
    if (j < 768)       v = bq[l * 768 + j];
    else if (j < 1536) v = bk[l * 768 + j - 768];
    else               v = bv[l * 768 + j - 1536];
    out[i] = v;
}

/* transpose + hi/lo split: dst[n*K+k] = split(src[k*N+n]) */
__global__ void wsplit_kernel(const float* __restrict__ src, __nv_bfloat16* __restrict__ dh,
                              __nv_bfloat16* __restrict__ dl, int K, int N,
                              long long sStride, long long dStride) {
    __shared__ float t[32][33];
    int l = blockIdx.z;
    const float* s = src + (size_t)l * sStride;
    __nv_bfloat16* oh = dh + (size_t)l * dStride;
    __nv_bfloat16* ol = dl + (size_t)l * dStride;
    int k0 = blockIdx.x * 32, n0 = blockIdx.y * 32;
    int tx = threadIdx.x, ty = threadIdx.y;
#pragma unroll
    for (int i = 0; i < 32; i += 8) t[ty + i][tx] = s[(size_t)(k0 + ty + i) * N + n0 + tx];
    __syncthreads();
#pragma unroll
    for (int i = 0; i < 32; i += 8) {
        float v = t[tx][ty + i];
        __nv_bfloat16 h, lo; split1(v, h, lo);
        size_t o = (size_t)(n0 + ty + i) * K + k0 + tx;
        oh[o] = h; ol[o] = lo;
    }
}

__global__ void split_kernel(const float* __restrict__ s, __nv_bfloat16* __restrict__ oh,
                             __nv_bfloat16* __restrict__ ol, int n) {
    int i = blockIdx.x * blockDim.x + threadIdx.x;
    if (i < n) { __nv_bfloat16 h, l; split1(s[i], h, l); oh[i] = h; ol[i] = l; }
}

/* ------------------------- embedding + masked LN -------------------------- */
__global__ void embed_kernel(const float* __restrict__ we, const float* __restrict__ pe,
                             const float* __restrict__ lg, const float* __restrict__ lb,
                             const int* __restrict__ ids, const int* __restrict__ am,
                             float* __restrict__ out, __nv_bfloat16* __restrict__ outh,
                             __nv_bfloat16* __restrict__ outl) {
    __shared__ float red[256];
    int row = blockIdx.x, tid = threadIdx.x;
    int s = row & (SQ - 1);
    int id = ids[row];
    float v[3];
#pragma unroll
    for (int i = 0; i < 3; i++) {
        int c = tid + i * 256;
        v[i] = we[(size_t)id * HID + c] + pe[(size_t)s * HID + c];
    }
    float sum = v[0] + v[1] + v[2];
    red[tid] = sum; __syncthreads();
    for (int st = 128; st > 0; st >>= 1) { if (tid < st) red[tid] += red[tid + st]; __syncthreads(); }
    float mu = red[0] * (1.0f / HID); __syncthreads();
    float s2 = 0.f;
#pragma unroll
    for (int i = 0; i < 3; i++) { float d = v[i] - mu; s2 += d * d; }
    red[tid] = s2; __syncthreads();
    for (int st = 128; st > 0; st >>= 1) { if (tid < st) red[tid] += red[tid + st]; __syncthreads(); }
    float r = rsqrtf(red[0] * (1.0f / HID) + 1e-7f);
    float mf = (float)am[row];
    size_t rb = (size_t)row * HID;
#pragma unroll
    for (int i = 0; i < 3; i++) {
        int c = tid + i * 256;
        float o = ((v[i] - mu) * r * lg[c] + lb[c]) * mf;
        out[rb + c] = o;
        __nv_bfloat16 h, l; split1(o, h, l);
        outh[rb + c] = h; outl[rb + c] = l;
    }
}

/* ------------------------- layernorm (+ optional hi/lo) ------------------- */
__global__ void ln_kernel(const float* __restrict__ in, const float* __restrict__ lg,
                          const float* __restrict__ lb, float* __restrict__ out,
                          __nv_bfloat16* __restrict__ outh, __nv_bfloat16* __restrict__ outl) {
    __shared__ float red[256];
    int row = blockIdx.x, tid = threadIdx.x;
    const float* xr = in + (size_t)row * HID;
    float v[3];
#pragma unroll
    for (int i = 0; i < 3; i++) v[i] = xr[tid + i * 256];
    float sum = v[0] + v[1] + v[2];
    red[tid] = sum; __syncthreads();
    for (int st = 128; st > 0; st >>= 1) { if (tid < st) red[tid] += red[tid + st]; __syncthreads(); }
    float mu = red[0] * (1.0f / HID); __syncthreads();
    float s2 = 0.f;
#pragma unroll
    for (int i = 0; i < 3; i++) { float d = v[i] - mu; s2 += d * d; }
    red[tid] = s2; __syncthreads();
    for (int st = 128; st > 0; st >>= 1) { if (tid < st) red[tid] += red[tid + st]; __syncthreads(); }
    float r = rsqrtf(red[0] * (1.0f / HID) + 1e-7f);
    size_t rb = (size_t)row * HID;
#pragma unroll
    for (int i = 0; i < 3; i++) {
        int c = tid + i * 256;
        float o = (v[i] - mu) * r * lg[c] + lb[c];
        out[rb + c] = o;
        if (outh) { __nv_bfloat16 h, l; split1(o, h, l); outh[rb + c] = h; outl[rb + c] = l; }
    }
}

/* ------------------------- softmax (gather + mask -> bf16 hi/lo) ---------- */
__global__ void attn_softmax_kernel(const float* __restrict__ sc, const float* __restrict__ c2p,
                                    const float* __restrict__ p2c, const int* __restrict__ am,
                                    __nv_bfloat16* __restrict__ ph, __nv_bfloat16* __restrict__ pl) {
    int q = blockIdx.x, bh = blockIdx.y;
    int b = bh / NHEAD;
    const float inv_scale = 0.07216878364870322f;
    const float* row  = sc  + ((size_t)bh * SQ + q) * SQ;
    const float* crow = c2p + ((size_t)bh * SQ + q) * SQ;
    const float* pbh  = p2c + (size_t)bh * SQ * SQ;
    int tid = threadIdx.x;
    bool mq = am[b * SQ + q] != 0;

    float v[2]; bool ok[2];
    float lmax = -3.402823466e38f;
#pragma unroll
    for (int i = 0; i < 2; i++) {
        int k = tid + i * 256;
        int di = q - k + 511;
        float s = (row[k] + crow[g_cidx[di]] + pbh[(size_t)k * SQ + g_pidx[di]]) * inv_scale;
        ok[i] = mq && (am[b * SQ + k] != 0);
        v[i] = ok[i] ? s : -3.402823466e38f;
        lmax = fmaxf(lmax, v[i]);
    }
    __shared__ float red[256];
    red[tid] = lmax; __syncthreads();
    for (int st = 128; st > 0; st >>= 1) { if (tid < st) red[tid] = fmaxf(red[tid], red[tid + st]); __syncthreads(); }
    float m = red[0]; __syncthreads();
    float ls = 0.f;
#pragma unroll
    for (int i = 0; i < 2; i++) { float e = expf(v[i] - m); v[i] = e; ls += e; }
    red[tid] = ls; __syncthreads();
    for (int st = 128; st > 0; st >>= 1) { if (tid < st) red[tid] += red[tid + st]; __syncthreads(); }
    float inv = 1.0f / red[0];
    size_t ob = ((size_t)bh * SQ + q) * SQ;
#pragma unroll
    for (int i = 0; i < 2; i++) {
        int k = tid + i * 256;
        float p = ok[i] ? v[i] * inv : 0.0f;
        __nv_bfloat16 h, l; split1(p, h, l);
        ph[ob + k] = h; pl[ob + k] = l;
    }
}

/* ------------------------- mma.sync split-bf16 GEMM (2-stage pipe) -------- */
#define KC 64
#define ABYTES 16384   /* 128 rows x 128B */

#define FL_GELU 1
#define FL_RES  2
#define FL_F32  4
#define FL_HILO 8
#define FL_QKV  64
#define FL_PQK  128

__device__ __forceinline__ void epi_pair(
    float v0, float v1, int m, int n,
    const float* bias, const float* Rb, float* Cf,
    __nv_bfloat16* Chi, __nv_bfloat16* Clo,
    int ldc, int ldh, size_t cfoff, size_t hoff, int flags)
{
    if (bias) { v0 += __ldg(bias + n); v1 += __ldg(bias + n + 1); }
    if (flags & FL_RES) {
        float2 rv = *reinterpret_cast<const float2*>(Rb + (size_t)m * ldc + n);
        v0 += rv.x; v1 += rv.y;
    }
    if (flags & FL_GELU) {
        v0 = 0.5f * v0 * (1.0f + erff(v0 * 0.70710678118654752f));
        v1 = 0.5f * v1 * (1.0f + erff(v1 * 0.70710678118654752f));
    }
    if (flags & FL_F32) {
        float2* p = reinterpret_cast<float2*>(Cf + cfoff + (size_t)m * ldc + n);
        *p = make_float2(v0, v1);
    }
    if (flags & FL_QKV) {
        int r = n / 768, nr = n - r * 768;
        __nv_bfloat16 h0, l0, h1, l1;
        split1(v0, h0, l0); split1(v1, h1, l1);
        if (r < 2) {
            size_t base = (size_t)r * ((size_t)ROWS * HID)
                        + (size_t)(m >> 9) * ((size_t)NHEAD * HD) + (size_t)(nr >> 6) * HD
                        + (size_t)(m & 511) * 64 + (nr & 63);
            __nv_bfloat162 hh; hh.x = h0; hh.y = h1;
            __nv_bfloat162 ll; ll.x = l0; ll.y = l1;
            *reinterpret_cast<uint32_t*>(Chi + base) = *reinterpret_cast<uint32_t*>(&hh);
            *reinterpret_cast<uint32_t*>(Clo + base) = *reinterpret_cast<uint32_t*>(&ll);
        } else {
            size_t vb = (size_t)2 * ((size_t)ROWS * HID);
            size_t i0 = vb + ((size_t)(m >> 9) * NHEAD + (nr >> 6)) * ((size_t)64 * SQ)
                      + (size_t)(nr & 63) * SQ + (m & 511);
            size_t i1 = vb + ((size_t)(m >> 9) * NHEAD + ((nr + 1) >> 6)) * ((size_t)64 * SQ)
                      + (size_t)((nr + 1) & 63) * SQ + (m & 511);
            Chi[i0] = h0; Clo[i0] = l0;
            Chi[i1] = h1; Clo[i1] = l1;
        }
        return;
    }
    if (flags & FL_PQK) {
        int r = n / 768, nr = n - r * 768;
        size_t base = (size_t)r * ((size_t)NHEAD * HD) + (size_t)(nr >> 6) * HD
                    + (size_t)m * 64 + (nr & 63);
        __nv_bfloat16 h0, l0, h1, l1;
        split1(v0, h0, l0); split1(v1, h1, l1);
        __nv_bfloat162 hh; hh.x = h0; hh.y = h1;
        __nv_bfloat162 ll; ll.x = l0; ll.y = l1;
        *reinterpret_cast<uint32_t*>(Chi + base) = *reinterpret_cast<uint32_t*>(&hh);
        *reinterpret_cast<uint32_t*>(Clo + base) = *reinterpret_cast<uint32_t*>(&ll);
        return;
    }
    if (flags & FL_HILO) {
        size_t base = hoff + (size_t)m * ldh + n;
        __nv_bfloat16 h0, l0, h1, l1;
        split1(v0, h0, l0); split1(v1, h1, l1);
        __nv_bfloat162 hh; hh.x = h0; hh.y = h1;
        __nv_bfloat162 ll; ll.x = l0; ll.y = l1;
        *reinterpret_cast<uint32_t*>(Chi + base) = *reinterpret_cast<uint32_t*>(&hh);
        *reinterpret_cast<uint32_t*>(Clo + base) = *reinterpret_cast<uint32_t*>(&ll);
    }
}

template<int TN>
__device__ __forceinline__ void load_chunk(
    uint32_t sst, const __nv_bfloat16* Azh, const __nv_bfloat16* Azl,
    const __nv_bfloat16* Bzh, const __nv_bfloat16* Bzl,
    int m0, int n0, int k0, int lda, int ldb, int tid)
{
    const uint32_t oAl = ABYTES, oBh = 2 * ABYTES, oBl = 2 * ABYTES + TN * 128;
#pragma unroll
    for (int i = 0; i < 4; i++) {
        int q = tid + i * 256;
        int row = q >> 3, quad = q & 7;
        size_t goff = (size_t)(m0 + row) * lda + k0 + quad * 8;
        uint32_t so = SWZ(row * 128 + quad * 16);
        CPA16(sst + so, Azh + goff);
        CPA16(sst + oAl + so, Azl + goff);
    }
#pragma unroll
    for (int i = 0; i < TN / 32; i++) {
        int q = tid + i * 256;
        int row = q >> 3, quad = q & 7;
        size_t goff = (size_t)(n0 + row) * ldb + k0 + quad * 8;
        uint32_t so = SWZ(row * 128 + quad * 16);
        CPA16(sst + oBh + so, Bzh + goff);
        CPA16(sst + oBl + so, Bzl + goff);
    }
    CPA_COMMIT();
}

template<int TN>
__global__ __launch_bounds__(256, (TN == 64) ? 2 : 1)
void hmma_kernel(const __nv_bfloat16* __restrict__ Ah, const __nv_bfloat16* __restrict__ Al,
                 const __nv_bfloat16* __restrict__ Bh, const __nv_bfloat16* __restrict__ Bl,
                 const float* __restrict__ bias, const float* __restrict__ Rb,
                 float* __restrict__ Cf, __nv_bfloat16* __restrict__ Chi, __nv_bfloat16* __restrict__ Clo,
                 int K, int lda, int ldb, int ldc, int ldh,
                 long long sAb, long long sAh_, long long sBb, long long sBh_,
                 long long sCb, long long sCh_, long long sHb, long long sHh_,
                 int nh, int flags)
{
    extern __shared__ char smem[];
    const int STAGE = 2 * ABYTES + 2 * TN * 128;
    uint32_t sb = smem_u32(smem);

    int tid = threadIdx.x, wid = tid >> 5, lane = tid & 31;
    int z = blockIdx.z, bo = z / nh, ho = z - bo * nh;
    int m0 = blockIdx.y * 128, n0 = blockIdx.x * TN;

    const __nv_bfloat16* Azh = Ah + (size_t)bo * sAb + (size_t)ho * sAh_;
    const __nv_bfloat16* Azl = Al + (size_t)bo * sAb + (size_t)ho * sAh_;
    const __nv_bfloat16* Bzh = Bh + (size_t)bo * sBb + (size_t)ho * sBh_;
    const __nv_bfloat16* Bzl = Bl + (size_t)bo * sBb + (size_t)ho * sBh_;

    const int MI = (TN == 128) ? 2 : 1;
    int wm = (TN == 128) ? (wid & 3) * 32 : wid * 16;
    int wn = (TN == 128) ? (wid >> 2) * 64 : 0;

    float acc[(TN == 128) ? 2 : 1][8][4];
#pragma unroll
    for (int a = 0; a < MI; a++)
#pragma unroll
        for (int b = 0; b < 8; b++)
#pragma unroll
            for (int c = 0; c < 4; c++) acc[a][b][c] = 0.f;

    int nch = K / KC;
    load_chunk<TN>(sb, Azh, Azl, Bzh, Bzl, m0, n0, 0, lda, ldb, tid);

    for (int ch = 0; ch < nch; ch++) {
        if (ch + 1 < nch) {
            load_chunk<TN>(sb + ((ch + 1) & 1) * STAGE, Azh, Azl, Bzh, Bzl,
                           m0, n0, (ch + 1) * KC, lda, ldb, tid);
            CPA_WAIT1();
        } else {
            CPA_WAIT0();
        }
        __syncthreads();

        uint32_t st = sb + (ch & 1) * STAGE;
        const uint32_t oAl = ABYTES, oBh = 2 * ABYTES, oBl = 2 * ABYTES + TN * 128;
#pragma unroll
        for (int ks = 0; ks < 4; ks++) {
            uint32_t ah[MI][4], al[MI][4];
#pragma unroll
            for (int mi = 0; mi < MI; mi++) {
                ldm4(ah[mi], amat_addr(st, wm + mi * 16, ks, lane));
                ldm4(al[mi], amat_addr(st + oAl, wm + mi * 16, ks, lane));
            }
#pragma unroll
            for (int ngp = 0; ngp < 4; ngp += 2) {
                uint32_t b0h[4], b1h[4], b0l[4], b1l[4];
                ldm4(b0h, bmat_addr(st + oBh, wn + ngp * 16, ks, lane));
                ldm4(b1h, bmat_addr(st + oBh, wn + (ngp + 1) * 16, ks, lane));
                ldm4(b0l, bmat_addr(st + oBl, wn + ngp * 16, ks, lane));
                ldm4(b1l, bmat_addr(st + oBl, wn + (ngp + 1) * 16, ks, lane));
#pragma unroll
                for (int mi = 0; mi < MI; mi++) {
                    mma16816(acc[mi][2 * ngp],     ah[mi], b0h[0], b0h[1]);
                    mma16816(acc[mi][2 * ngp + 1], ah[mi], b0h[2], b0h[3]);
                    mma16816(acc[mi][2 * ngp + 2], ah[mi], b1h[0], b1h[1]);
                    mma16816(acc[mi][2 * ngp + 3], ah[mi], b1h[2], b1h[3]);
                }
#pragma unroll
                for (int mi = 0; mi < MI; mi++) {
                    mma16816(acc[mi][2 * ngp],     ah[mi], b0l[0], b0l[1]);
                    mma16816(acc[mi][2 * ngp + 1], ah[mi], b0l[2], b0l[3]);
                    mma16816(acc[mi][2 * ngp + 2], ah[mi], b1l[0], b1l[1]);
                    mma16816(acc[mi][2 * ngp + 3], ah[mi], b1l[2], b1l[3]);
                }
#pragma unroll
                for (int mi = 0; mi < MI; mi++) {
                    mma16816(acc[mi][2 * ngp],     al[mi], b0h[0], b0h[1]);
                    mma16816(acc[mi][2 * ngp + 1], al[mi], b0h[2], b0h[3]);
                    mma16816(acc[mi][2 * ngp + 2], al[mi], b1h[0], b1h[1]);
                    mma16816(acc[mi][2 * ngp + 3], al[mi], b1h[2], b1h[3]);
                }
            }
        }
        __syncthreads();
    }

    size_t cfoff = (size_t)bo * sCb + (size_t)ho * sCh_;
    size_t hoff  = (size_t)bo * sHb + (size_t)ho * sHh_;
    int r0 = lane >> 2, cc = (lane & 3) * 2;
#pragma unroll
    for (int mi = 0; mi < MI; mi++) {
#pragma unroll
        for (int nf = 0; nf < 8; nf++) {
            int m_ = m0 + wm + mi * 16 + r0;
            int n_ = n0 + wn + nf * 8 + cc;
            epi_pair(acc[mi][nf][0], acc[mi][nf][1], m_,     n_, bias, Rb, Cf, Chi, Clo, ldc, ldh, cfoff, hoff, flags);
            epi_pair(acc[mi][nf][2], acc[mi][nf][3], m_ + 8, n_, bias, Rb, Cf, Chi, Clo, ldc, ldh, cfoff, hoff, flags);
        }
    }
}

/* ------------------------- host-side GEMM wrapper ------------------------- */
#define STAGE128 (2 * ABYTES + 2 * 128 * 128)
#define STAGE64  (2 * ABYTES + 2 * 64 * 128)

static void tmma(const __nv_bfloat16* Ah, const __nv_bfloat16* Al,
                 const __nv_bfloat16* Bh, const __nv_bfloat16* Bl,
                 const float* bias, const float* Rb,
                 float* Cf, __nv_bfloat16* Chi, __nv_bfloat16* Clo,
                 int M, int N, int K, int lda, int ldb, int ldc, int ldh,
                 long long sAb, long long sAh, long long sBb, long long sBh,
                 long long sCb, long long sCh, long long sHb, long long sHh,
                 int nh, int nz, int flags)
{
    int stages = (K <= KC) ? 1 : 2;
    if (N >= 1024) {
        dim3 g(N / 128, M / 128, nz);
        hmma_kernel<128><<<g, 256, stages * STAGE128>>>(Ah, Al, Bh, Bl, bias, Rb, Cf, Chi, Clo,
            K, lda, ldb, ldc, ldh, sAb, sAh, sBb, sBh, sCb, sCh, sHb, sHh, nh, flags);
    } else {
        dim3 g(N / 64, M / 128, nz);
        hmma_kernel<64><<<g, 256, stages * STAGE64>>>(Ah, Al, Bh, Bl, bias, Rb, Cf, Chi, Clo,
            K, lda, ldb, ldc, ldh, sAb, sAh, sBb, sBh, sCb, sCh, sHb, sHh, nh, flags);
    }
}

extern "C" void kernel_launch(void* const* d_in, const int* in_sizes, int n_in,
                              void* d_out, int out_size) {
    const float* word_emb = (const float*)d_in[0];
    const float* pos_emb  = (const float*)d_in[1];
    const float* emb_ln_g = (const float*)d_in[2];
    const float* emb_ln_b = (const float*)d_in[3];
    const float* rel_emb  = (const float*)d_in[4];
    const float* Wq = (const float*)d_in[5];
    const float* bq = (const float*)d_in[6];
    const float* Wk = (const float*)d_in[7];
    const float* bk = (const float*)d_in[8];
    const float* Wv = (const float*)d_in[9];
    const float* bv = (const float*)d_in[10];
    const float* Wo = (const float*)d_in[11];
    const float* bo = (const float*)d_in[12];
    const float* ln1_g = (const float*)d_in[13];
    const float* ln1_b = (const float*)d_in[14];
    const float* Wi = (const float*)d_in[15];
    const float* bi = (const float*)d_in[16];
    const float* Wo2 = (const float*)d_in[17];
    const float* bo2 = (const float*)d_in[18];
    const float* ln2_g = (const float*)d_in[19];
    const float* ln2_b = (const float*)d_in[20];
    const int* input_ids = (const int*)d_in[21];
    const int* attn_mask = (const int*)d_in[22];
    float* out = (float*)d_out;

    cudaFuncSetAttribute(hmma_kernel<128>, cudaFuncAttributeMaxDynamicSharedMemorySize, 2 * STAGE128);
    cudaFuncSetAttribute(hmma_kernel<64>,  cudaFuncAttributeMaxDynamicSharedMemorySize, 2 * STAGE64);

    float *x, *h1, *tmp, *sc, *c2p, *p2c, *qkvb;
    __nv_bfloat16 *xh, *xl, *h1h, *h1l, *qkvh, *qkvl, *ctxh, *ctxl;
    __nv_bfloat16 *ffh, *ffl, *pqkh, *pqkl, *relh, *rell, *wth, *wtl, *ph, *pl;
    cudaGetSymbolAddress((void**)&x, g_x);       cudaGetSymbolAddress((void**)&h1, g_h1);
    cudaGetSymbolAddress((void**)&tmp, g_tmp);
    cudaGetSymbolAddress((void**)&sc, g_sc);     cudaGetSymbolAddress((void**)&c2p, g_c2p);
    cudaGetSymbolAddress((void**)&p2c, g_p2c);
    cudaGetSymbolAddress((void**)&xh, g_xh);     cudaGetSymbolAddress((void**)&xl, g_xl);
    cudaGetSymbolAddress((void**)&h1h, g_h1h);   cudaGetSymbolAddress((void**)&h1l, g_h1l);
    cudaGetSymbolAddress((void**)&qkvh, g_qkvh); cudaGetSymbolAddress((void**)&qkvl, g_qkvl);
    cudaGetSymbolAddress((void**)&ctxh, g_ctxh); cudaGetSymbolAddress((void**)&ctxl, g_ctxl);
    cudaGetSymbolAddress((void**)&ffh, g_ffh);   cudaGetSymbolAddress((void**)&ffl, g_ffl);
    cudaGetSymbolAddress((void**)&pqkh, g_pqkh); cudaGetSymbolAddress((void**)&pqkl, g_pqkl);
    cudaGetSymbolAddress((void**)&relh, g_relh); cudaGetSymbolAddress((void**)&rell, g_rell);
    cudaGetSymbolAddress((void**)&wth, g_wth);   cudaGetSymbolAddress((void**)&wtl, g_wtl);
    cudaGetSymbolAddress((void**)&ph, g_ph);     cudaGetSymbolAddress((void**)&pl, g_pl);
    cudaGetSymbolAddress((void**)&qkvb, g_qkvb);

    __nv_bfloat16 *qh = qkvh,                      *ql = qkvl;
    __nv_bfloat16 *kh = qkvh + (size_t)ROWS * HID, *kl = qkvl + (size_t)ROWS * HID;
    __nv_bfloat16 *vth = qkvh + (size_t)2 * ROWS * HID, *vtl = qkvl + (size_t)2 * ROWS * HID;
    __nv_bfloat16 *pqh = pqkh,             *pql = pqkl;
    __nv_bfloat16 *pkh = pqkh + NHEAD * HD, *pkl = pqkl + NHEAD * HD;

    build_tables_kernel<<<1, 1024>>>();
    qkvbias_kernel<<<(NLAYER * 2304 + 255) / 256, 256>>>(bq, bk, bv, qkvb);

    dim3 tb(32, 8);
    wsplit_kernel<<<dim3(HID/32, HID/32, NLAYER), tb>>>(Wq,  wth + 0*WSZ,        wtl + 0*WSZ,        HID, HID,   (long long)WSZ,  (long long)LOFF);
    wsplit_kernel<<<dim3(HID/32, HID/32, NLAYER), tb>>>(Wk,  wth + 1*WSZ,        wtl + 1*WSZ,        HID, HID,   (long long)WSZ,  (long long)LOFF);
    wsplit_kernel<<<dim3(HID/32, HID/32, NLAYER), tb>>>(Wv,  wth + 2*WSZ,        wtl + 2*WSZ,        HID, HID,   (long long)WSZ,  (long long)LOFF);
    wsplit_kernel<<<dim3(HID/32, HID/32, NLAYER), tb>>>(Wo,  wth + 3*WSZ,        wtl + 3*WSZ,        HID, HID,   (long long)WSZ,  (long long)LOFF);
    wsplit_kernel<<<dim3(HID/32, FFDIM/32, NLAYER), tb>>>(Wi,  wth + 4*WSZ,      wtl + 4*WSZ,        HID, FFDIM, (long long)WISZ, (long long)LOFF);
    wsplit_kernel<<<dim3(FFDIM/32, HID/32, NLAYER), tb>>>(Wo2, wth + 4*WSZ+WISZ, wtl + 4*WSZ+WISZ,   FFDIM, HID, (long long)WISZ, (long long)LOFF);
    split_kernel<<<(SQ*HID + 255)/256, 256>>>(rel_emb, relh, rell, SQ*HID);

    embed_kernel<<<ROWS, 256>>>(word_emb, pos_emb, emb_ln_g, emb_ln_b, input_ids, attn_mask, x, xh, xl);

    const long long SS = (long long)SQ * SQ;
    const long long HSS = (long long)NHEAD * SS;
    const long long SHD = (long long)HD;
    const long long BHD = (long long)NHEAD * HD;

    for (int l = 0; l < NLAYER; l++) {
        const __nv_bfloat16 *WqTh = wth + (size_t)l*LOFF, *WqTl = wtl + (size_t)l*LOFF;
        const __nv_bfloat16 *WoTh = WqTh + 3*WSZ, *WoTl = WqTl + 3*WSZ;
        const __nv_bfloat16 *WiTh = WqTh + 4*WSZ, *WiTl = WqTl + 4*WSZ;
        const __nv_bfloat16 *W2Th = WqTh + 4*WSZ + WISZ, *W2Tl = WqTl + 4*WSZ + WISZ;
        const float *qkvb_l = qkvb + (size_t)l * 2304;
        const float *bo_l = bo + (size_t)l*HID, *bi_l = bi + (size_t)l*FFDIM, *bo2_l = bo2 + (size_t)l*HID;

        /* fused QKV projection: B = [WqT|WkT|WvT] (contiguous), N=2304 */
        tmma(xh, xl, WqTh, WqTl, qkvb_l, nullptr, nullptr, qkvh, qkvl,
             ROWS, 2304, HID, HID, HID, 0, 0, 0,0,0,0, 0,0,0,0, 1, 1, FL_QKV);
        /* fused pos projections: B = [WqT|WkT], N=1536 -> pq | pk */
        tmma(relh, rell, WqTh, WqTl, qkvb_l, nullptr, nullptr, pqkh, pqkl,
             SQ, 1536, HID, HID, HID, 0, 0, 0,0,0,0, 0,0,0,0, 1, 1, FL_PQK);

        tmma(qh, ql, kh, kl, nullptr, nullptr, sc, nullptr, nullptr,
             SQ, SQ, DHEAD, DHEAD, DHEAD, SQ, 0,
             BHD, SHD, BHD, SHD, HSS, SS, 0, 0, NHEAD, BHT, FL_F32);
        tmma(qh, ql, pkh, pkl, nullptr, nullptr, c2p, nullptr, nullptr,
             SQ, SQ, DHEAD, DHEAD, DHEAD, SQ, 0,
             BHD, SHD, 0, SHD, HSS, SS, 0, 0, NHEAD, BHT, FL_F32);
        tmma(kh, kl, pqh, pql, nullptr, nullptr, p2c, nullptr, nullptr,
             SQ, SQ, DHEAD, DHEAD, DHEAD, SQ, 0,
             BHD, SHD, 0, SHD, HSS, SS, 0, 0, NHEAD, BHT, FL_F32);

        attn_softmax_kernel<<<dim3(SQ, BHT), 256>>>(sc, c2p, p2c, attn_mask, ph, pl);

        tmma(ph, pl, vth, vtl, nullptr, nullptr, nullptr, ctxh, ctxl,
             SQ, DHEAD, SQ, SQ, SQ, 0, HID,
             HSS, SS, BHD, SHD, 0, 0, (long long)SQ*HID, DHEAD, NHEAD, BHT, FL_HILO);

        tmma(ctxh, ctxl, WoTh, WoTl, bo_l, x, tmp, nullptr, nullptr,
             ROWS, HID, HID, HID, HID, HID, 0, 0,0,0,0, 0,0,0,0, 1, 1, FL_F32 | FL_RES);
        ln_kernel<<<ROWS, 256>>>(tmp, ln1_g + (size_t)l*HID, ln1_b + (size_t)l*HID, h1, h1h, h1l);

        tmma(h1h, h1l, WiTh, WiTl, bi_l, nullptr, nullptr, ffh, ffl,
             ROWS, FFDIM, HID, HID, HID, 0, FFDIM, 0,0,0,0, 0,0,0,0, 1, 1, FL_GELU | FL_HILO);
        tmma(ffh, ffl, W2Th, W2Tl, bo2_l, h1, tmp, nullptr, nullptr,
             ROWS, HID, FFDIM, FFDIM, FFDIM, HID, 0, 0,0,0,0, 0,0,0,0, 1, 1, FL_F32 | FL_RES);
        ln_kernel<<<ROWS, 256>>>(tmp, ln2_g + (size_t)l*HID, ln2_b + (size_t)l*HID,
                                 (l == NLAYER - 1) ? out : x,
                                 (l == NLAYER - 1) ? nullptr : xh,
                                 (l == NLAYER - 1) ? nullptr : xl);
    }
}